// round 11
// baseline (speedup 1.0000x reference)
#include <cuda_runtime.h>
#include <cuda_bf16.h>
#include <cuda_fp16.h>
#include <mma.h>
#include <cstdint>
using namespace nvcuda;

#define B_ 8
#define T_ 2048
#define S_ 512
#define VD_ 512
#define AD_ 256
#define E_ 512
#define H_ 8
#define BH_ 64

__device__ __half g_q [(size_t)BH_*T_*64];
__device__ __half g_k [(size_t)BH_*S_*64];
__device__ __half g_vv[(size_t)BH_*T_*64];
__device__ __half g_va[(size_t)BH_*S_*64];
__device__ __half g_v2[(size_t)BH_*S_*64];          // va / l
__device__ __half g_p [(size_t)BH_*S_*T_];          // exp2(S) fp16
__device__ __nv_bfloat16 g_ovh[(size_t)B_*T_*E_], g_ovl[(size_t)B_*T_*E_];
__device__ __nv_bfloat16 g_oah[(size_t)B_*S_*E_], g_oal[(size_t)B_*S_*E_];

__device__ __forceinline__ float ex2f(float x) {
    float r; asm("ex2.approx.f32 %0, %1;" : "=f"(r) : "f"(x)); return r;
}
__device__ __forceinline__ uint32_t cvta_s(const void* p) {
    uint32_t r;
    asm("{ .reg .u64 t; cvta.to.shared.u64 t, %1; cvt.u32.u64 %0, t; }" : "=r"(r) : "l"(p));
    return r;
}
__device__ __forceinline__ uint32_t h2u(float x, float y) {
    __half2 h = __floats2half2_rn(x, y); return *(uint32_t*)&h;
}
__device__ __forceinline__ void split2(float x, __nv_bfloat16& h, __nv_bfloat16& l) {
    h = __float2bfloat16(x);
    l = __float2bfloat16(x - __bfloat162float(h));
}
__device__ __forceinline__ void split8(const float* x, uint4& uh, uint4& ul) {
    union { __nv_bfloat16 b[8]; uint4 u; } Hh, Ll;
    #pragma unroll
    for (int j = 0; j < 8; j++) {
        __nv_bfloat16 hb = __float2bfloat16(x[j]);
        Hh.b[j] = hb; Ll.b[j] = __float2bfloat16(x[j] - __bfloat162float(hb));
    }
    uh = Hh.u; ul = Ll.u;
}
__device__ __forceinline__ uint4 pack8h(const float* x) {
    union { __half b[8]; uint4 u; } U;
    #pragma unroll
    for (int j = 0; j < 8; j++) U.b[j] = __float2half_rn(x[j]);
    return U.u;
}
__device__ __forceinline__ void ldsm4(uint32_t& r0, uint32_t& r1, uint32_t& r2, uint32_t& r3,
                                      uint32_t a) {
    asm volatile("ldmatrix.sync.aligned.m8n8.x4.shared.b16 {%0,%1,%2,%3}, [%4];"
                 : "=r"(r0), "=r"(r1), "=r"(r2), "=r"(r3) : "r"(a));
}
__device__ __forceinline__ void ldsm4t(uint32_t& r0, uint32_t& r1, uint32_t& r2, uint32_t& r3,
                                       uint32_t a) {
    asm volatile("ldmatrix.sync.aligned.m8n8.x4.trans.shared.b16 {%0,%1,%2,%3}, [%4];"
                 : "=r"(r0), "=r"(r1), "=r"(r2), "=r"(r3) : "r"(a));
}
__device__ __forceinline__ void mma4(float* c, const uint32_t* a, uint32_t b0, uint32_t b1) {
    asm volatile("mma.sync.aligned.m16n8k16.row.col.f32.f16.f16.f32 "
                 "{%0,%1,%2,%3}, {%4,%5,%6,%7}, {%8,%9}, {%0,%1,%2,%3};"
                 : "+f"(c[0]), "+f"(c[1]), "+f"(c[2]), "+f"(c[3])
                 : "r"(a[0]), "r"(a[1]), "r"(a[2]), "r"(a[3]), "r"(b0), "r"(b1));
}
#define CP16(dst, src) \
    asm volatile("cp.async.cg.shared.global [%0], [%1], 16;" :: "r"(dst), "l"(src))
#define CPCOMMIT() asm volatile("cp.async.commit_group;" ::: "memory")

// ============ scores_p: P[s0:+128][t0:+128] = exp2(K @ Q^T), fp16 ==========
// One-shot tile, K=64. ex2 only in epilogue (no loop-carried deps).
#define SP_K  0
#define SP_Q  18432
#define SP_SZ 36864

__global__ void __launch_bounds__(256,2) scores_p()
{
    extern __shared__ char sm[];
    const uint32_t smb = cvta_s(sm);
    __half* PS = (__half*)sm;                       // staging reuses K/Q space

    const int tid = threadIdx.x, w = tid>>5, lane = tid&31;
    const int gid = lane>>2, tig = lane&3, wq = lane&7;
    const int wm = w&3, wn = w>>2;
    const int bh = blockIdx.z;
    const int s0 = blockIdx.y*128, t0 = blockIdx.x*128;

    {   // K tile 128x64 -> [0], Q tile 128x64 -> [SP_Q], stride 72 halves
        const uint4* ks = (const uint4*)(g_k + ((size_t)bh*S_+s0)*64);
        const uint4* qs = (const uint4*)(g_q + ((size_t)bh*T_+t0)*64);
        #pragma unroll
        for (int i = 0; i < 4; i++) {
            int q = tid + i*256, r = q>>3, c = q&7;
            *(uint4*)((__half*)sm + r*72 + c*8)          = ks[q];
            *(uint4*)((__half*)(sm+SP_Q) + r*72 + c*8)   = qs[q];
        }
    }
    __syncthreads();

    float acc[2][8][4] = {};
    const uint32_t qlo = smb + SP_Q + (uint32_t)((wq + ((lane>>4)&1)*8)*144) + ((lane>>3)&1)*16;
    #pragma unroll
    for (int ks = 0; ks < 4; ks++) {
        uint32_t A[2][4];
        #pragma unroll
        for (int i = 0; i < 2; i++) {
            uint32_t ad = smb + SP_K
                        + (uint32_t)(((wm*32+i*16+(lane&15))*72 + (lane>>4)*8)*2) + ks*32;
            ldsm4(A[i][0], A[i][1], A[i][2], A[i][3], ad);
        }
        #pragma unroll
        for (int jb = 0; jb < 4; jb++) {
            uint32_t q0,q1,q2,q3;
            ldsm4(q0,q1,q2,q3, qlo + (wn*64 + jb*16)*144 + ks*32);
            #pragma unroll
            for (int i = 0; i < 2; i++) {
                mma4(acc[i][jb*2],   A[i], q0, q1);
                mma4(acc[i][jb*2+1], A[i], q2, q3);
            }
        }
    }
    __syncthreads();
    {   // ex2 + pack -> PS (stride 136), then coalesced store
        #pragma unroll
        for (int i = 0; i < 2; i++)
            #pragma unroll
            for (int n8 = 0; n8 < 8; n8++) {
                int col = wn*64 + n8*8 + 2*tig;
                int r0 = wm*32 + i*16 + gid;
                *(uint32_t*)(PS + r0*136 + col) =
                    h2u(ex2f(acc[i][n8][0]), ex2f(acc[i][n8][1]));
                *(uint32_t*)(PS + (r0+8)*136 + col) =
                    h2u(ex2f(acc[i][n8][2]), ex2f(acc[i][n8][3]));
            }
    }
    __syncthreads();
    {
        int r = tid>>1, c0 = (tid&1)*64;
        const __half* ps = PS + r*136 + c0;
        __half* gp = g_p + ((size_t)(bh*S_+s0+r))*T_ + t0 + c0;
        #pragma unroll
        for (int i = 0; i < 8; i++)
            *(uint4*)(gp + i*8) = *(const uint4*)(ps + i*8);
    }
}

// ============ gemm_outa: out_a = (P @ vv)/l ; va2 = va/l ===================
// s-tile 128 x 64d per block; K = T = 2048 in 64 chunks of 32; l from A-frags.
#define OA_VB 30720
#define OA_LS 45056
#define OA_SZ 45568

__global__ void __launch_bounds__(256,2) gemm_outa()
{
    extern __shared__ char sm[];
    const uint32_t smb = cvta_s(sm);
    float* lsm = (float*)(sm + OA_LS);
    float* OS  = (float*)sm;

    const int tid = threadIdx.x, w = tid>>5, lane = tid&31;
    const int wm = w&3, wn = w>>2;
    const int gid = lane>>2, tig = lane&3, wq = lane&7;
    const int bh = blockIdx.y, b = bh>>3, h = bh&7;
    const int s0 = blockIdx.x*128;

    // P chunk [128 s][32 t] stride 40 halves; 2 CP16 per thread
    const int pr = tid>>1, pc = (tid&1)*16;         // halves: pc in {0,16}
    const __half* psrc = g_p + (size_t)(bh*S_ + s0 + pr)*T_ + pc;
    const uint32_t pdst = smb + (uint32_t)(pr*80 + pc*2);
    // vv chunk [32 t][64 d] stride 72; 1 CP16 per thread
    const int vr = tid>>3, vc = tid&7;
    const __half* vsrc = g_vv + (size_t)bh*T_*64 + (size_t)vr*64 + vc*8;
    const uint32_t vdst = smb + OA_VB + (uint32_t)(vr*144 + vc*16);

    #pragma unroll
    for (int c = 0; c < 2; c++) {
        CP16(pdst + c*10240,      psrc + (size_t)c*32);
        CP16(pdst + c*10240 + 16, psrc + (size_t)c*32 + 8);
        CP16(vdst + c*4608,       vsrc + (size_t)c*32*64);
        CPCOMMIT();
    }

    float acc[2][4][4] = {};
    float lr[2][2] = {};

    for (int c = 0; c < 64; c++) {
        if (c < 63) { asm volatile("cp.async.wait_group 1;" ::: "memory"); }
        else        { asm volatile("cp.async.wait_group 0;" ::: "memory"); }
        __syncthreads();
        if (c + 2 < 64) {
            int j = (c+2)%3;
            CP16(pdst + j*10240,      psrc + (size_t)(c+2)*32);
            CP16(pdst + j*10240 + 16, psrc + (size_t)(c+2)*32 + 8);
            CP16(vdst + j*4608,       vsrc + (size_t)(c+2)*32*64);
            CPCOMMIT();
        }
        const uint32_t pb = smb + (uint32_t)((c%3)*10240);
        const uint32_t vb = smb + OA_VB + (uint32_t)((c%3)*4608);
        #pragma unroll
        for (int ks = 0; ks < 2; ks++) {
            uint32_t aa[2][4];
            #pragma unroll
            for (int i = 0; i < 2; i++) {
                uint32_t ad = pb + (uint32_t)(((wm*32+i*16+(lane&15))*40
                             + ks*16 + (lane>>4)*8)*2);
                ldsm4(aa[i][0], aa[i][1], aa[i][2], aa[i][3], ad);
                if (wn == 0) {
                    float2 f0 = __half22float2(*(__half2*)&aa[i][0]);
                    float2 f2 = __half22float2(*(__half2*)&aa[i][2]);
                    float2 f1 = __half22float2(*(__half2*)&aa[i][1]);
                    float2 f3 = __half22float2(*(__half2*)&aa[i][3]);
                    lr[i][0] += f0.x+f0.y+f2.x+f2.y;
                    lr[i][1] += f1.x+f1.y+f3.x+f3.y;
                }
            }
            #pragma unroll
            for (int jn = 0; jn < 2; jn++) {
                uint32_t v0,v1,v2,v3;
                uint32_t bd = vb + (uint32_t)((ks*16 + wq + ((lane>>3)&1)*8)*144)
                            + (uint32_t)((wn*32 + jn*16)*2) + ((lane>>4)&1)*16;
                ldsm4t(v0,v1,v2,v3, bd);
                #pragma unroll
                for (int i = 0; i < 2; i++) {
                    mma4(acc[i][2*jn],   aa[i], v0, v1);
                    mma4(acc[i][2*jn+1], aa[i], v2, v3);
                }
            }
        }
        __syncthreads();
    }

    // l reduction over tig (k positions)
    #pragma unroll
    for (int i = 0; i < 2; i++)
        #pragma unroll
        for (int hh2 = 0; hh2 < 2; hh2++) {
            lr[i][hh2] += __shfl_xor_sync(0xffffffffu, lr[i][hh2], 1);
            lr[i][hh2] += __shfl_xor_sync(0xffffffffu, lr[i][hh2], 2);
        }
    if (wn == 0 && tig == 0) {
        #pragma unroll
        for (int i = 0; i < 2; i++) {
            lsm[wm*32 + i*16 + gid]     = lr[i][0];
            lsm[wm*32 + i*16 + gid + 8] = lr[i][1];
        }
    }
    __syncthreads();
    {   // acc/l -> OS
        #pragma unroll
        for (int i = 0; i < 2; i++) {
            int r0 = wm*32 + i*16 + gid;
            float inv0 = 1.0f/lsm[r0], inv1 = 1.0f/lsm[r0+8];
            #pragma unroll
            for (int nf = 0; nf < 4; nf++) {
                int cb = wn*32 + nf*8 + 2*tig;
                OS[r0*68 + cb]       = acc[i][nf][0]*inv0;
                OS[r0*68 + cb + 1]   = acc[i][nf][1]*inv0;
                OS[(r0+8)*68 + cb]   = acc[i][nf][2]*inv1;
                OS[(r0+8)*68 + cb+1] = acc[i][nf][3]*inv1;
            }
        }
    }
    __syncthreads();
    {
        int r = tid>>1, c0 = (tid&1)*32;
        float inv = 1.0f/lsm[r];
        float x[32];
        const float* row = OS + r*68 + c0;
        #pragma unroll
        for (int g4 = 0; g4 < 8; g4++) *(float4*)(x+g4*4) = *(const float4*)(row+g4*4);
        size_t o = ((size_t)(b*S_+s0+r))*E_ + h*64 + c0;
        #pragma unroll
        for (int g8 = 0; g8 < 4; g8++) {
            uint4 uh, ul; split8(x+g8*8, uh, ul);
            *(uint4*)(g_oah+o+g8*8) = uh; *(uint4*)(g_oal+o+g8*8) = ul;
        }
        size_t vi = ((size_t)(bh*S_+s0+r))*64 + c0;
        #pragma unroll
        for (int g8 = 0; g8 < 4; g8++) {
            uint4 wv = *(uint4*)(g_va + vi + g8*8);
            const __half* hp = (const __half*)&wv;
            float y[8];
            #pragma unroll
            for (int j = 0; j < 8; j++) y[j] = __half2float(hp[j]) * inv;
            *(uint4*)(g_v2 + vi + g8*8) = pack8h(y);
        }
    }
}

// ============ gemm_outv: out_v = P^T @ va2 (K=512) — unchanged R10 =========
#define FV_AB 26112
#define FV_SZ 39936

__global__ void __launch_bounds__(256,2) gemm_outv()
{
    extern __shared__ char sm[];
    const uint32_t smb = cvta_s(sm);
    float* OS = (float*)sm;

    const int tid = threadIdx.x, w = tid>>5, lane = tid&31;
    const int wm = w&3, wn = w>>2;
    const int gid = lane>>2, tig = lane&3;
    const int bh = blockIdx.y, b = bh>>3, h = bh&7;
    const int t0 = blockIdx.x*128;

    const int cr = tid>>3, cc = tid&7;
    const __half* psrc = g_p  + (size_t)(bh*S_ + cr)*T_ + t0 + cc*8;
    const __half* asrc = g_v2 + (size_t)(bh*S_ + cr)*64 + cc*8;
    const uint32_t pdst = smb + (uint32_t)(cr*272 + cc*16);
    const uint32_t adst = smb + FV_AB + (uint32_t)(cr*144 + cc*16);

    #pragma unroll
    for (int c = 0; c < 2; c++) {
        CP16(pdst + c*8704,       psrc + (size_t)c*32*T_);
        CP16(pdst + c*8704 + 128, psrc + (size_t)c*32*T_ + 64);
        CP16(adst + c*4608,       asrc + (size_t)c*32*64);
        CPCOMMIT();
    }

    float acc[2][4][4] = {};

    for (int c = 0; c < 16; c++) {
        if (c < 15) { asm volatile("cp.async.wait_group 1;" ::: "memory"); }
        else        { asm volatile("cp.async.wait_group 0;" ::: "memory"); }
        __syncthreads();
        if (c + 2 < 16) {
            int j = (c+2)%3;
            CP16(pdst + j*8704,       psrc + (size_t)(c+2)*32*T_);
            CP16(pdst + j*8704 + 128, psrc + (size_t)(c+2)*32*T_ + 64);
            CP16(adst + j*4608,       asrc + (size_t)(c+2)*32*64);
            CPCOMMIT();
        }
        const uint32_t pb = smb + (uint32_t)((c%3)*8704);
        const uint32_t ab = smb + FV_AB + (uint32_t)((c%3)*4608);
        #pragma unroll
        for (int ks = 0; ks < 2; ks++) {
            uint32_t aa[2][4];
            #pragma unroll
            for (int i = 0; i < 2; i++) {
                uint32_t ad = pb + (uint32_t)(((ks*16 + (lane&7) + ((lane>>4)&1)*8)*136
                              + wm*32 + i*16 + ((lane>>3)&1)*8)*2);
                ldsm4t(aa[i][0], aa[i][1], aa[i][2], aa[i][3], ad);
            }
            #pragma unroll
            for (int jn = 0; jn < 2; jn++) {
                uint32_t v0,v1,v2,v3;
                uint32_t bd = ab + (uint32_t)(((ks*16 + (lane&7) + ((lane>>3)&1)*8)*72
                              + wn*32 + jn*16 + ((lane>>4)&1)*8)*2);
                ldsm4t(v0,v1,v2,v3, bd);
                #pragma unroll
                for (int i = 0; i < 2; i++) {
                    mma4(acc[i][2*jn],   aa[i], v0, v1);
                    mma4(acc[i][2*jn+1], aa[i], v2, v3);
                }
            }
        }
        __syncthreads();
    }
    {
        #pragma unroll
        for (int i = 0; i < 2; i++)
            #pragma unroll
            for (int nf = 0; nf < 4; nf++) {
                int rr = wm*32 + i*16 + gid, cbase = wn*32 + nf*8 + 2*tig;
                OS[rr*68 + cbase]       = acc[i][nf][0];
                OS[rr*68 + cbase + 1]   = acc[i][nf][1];
                OS[(rr+8)*68 + cbase]   = acc[i][nf][2];
                OS[(rr+8)*68 + cbase+1] = acc[i][nf][3];
            }
    }
    __syncthreads();
    {
        int r = tid>>1, c0 = (tid&1)*32;
        float x[32];
        const float* row = OS + r*68 + c0;
        #pragma unroll
        for (int g4 = 0; g4 < 8; g4++) *(float4*)(x+g4*4) = *(const float4*)(row+g4*4);
        size_t o = ((size_t)(b*T_+t0+r))*E_ + h*64 + c0;
        #pragma unroll
        for (int g8 = 0; g8 < 4; g8++) {
            uint4 uh, ul; split8(x+g8*8, uh, ul);
            *(uint4*)(g_ovh+o+g8*8) = uh; *(uint4*)(g_ovl+o+g8*8) = ul;
        }
    }
}

// ---------------- projection GEMMs (bf16 3-term, 128x128, KC=32) -----------
using AccFrag = wmma::fragment<wmma::accumulator, 16, 16, 16, float>;
using FragAb = wmma::fragment<wmma::matrix_a, 16, 16, 16, __nv_bfloat16, wmma::row_major>;
using FragBb = wmma::fragment<wmma::matrix_b, 16, 16, 16, __nv_bfloat16, wmma::row_major>;
#define PJSZ 75776

template<int AP>
__device__ __forceinline__ void proj_main(char* smem, const float* A,
    const __nv_bfloat16* Aph, const __nv_bfloat16* Apl,
    const float* W, int K, int N, int m0, int n0, int tid, AccFrag (&acc)[2][4])
{
    const int wid = tid>>5, wm = wid&3, wn = wid>>2;
    auto Ab = [&](int bb, int pl) { return (__nv_bfloat16*)(smem + (bb*2+pl)*10240); };
    auto Bb = [&](int bb, int pl) { return (__nv_bfloat16*)(smem + 40960 + (bb*2+pl)*8704); };
    const int nc = K / 32;
    float4 ra[4]; uint4 rua[4]; float4 rb[4];

    auto ldg = [&](int k0) {
        if (AP == 0) {
            #pragma unroll
            for (int i=0;i<4;i++) {
                int q = tid + i*256, r = q>>3, c4 = (q&7)*4;
                ra[i] = *(const float4*)(A + (size_t)(m0+r)*K + k0 + c4);
            }
        } else {
            #pragma unroll
            for (int i=0;i<4;i++) {
                int pl = i>>1, cid = tid + (i&1)*256, r = cid>>2, c = cid&3;
                const __nv_bfloat16* src = (pl ? Apl : Aph) + (size_t)(m0+r)*K + k0;
                rua[i] = ((const uint4*)src)[c];
            }
        }
        #pragma unroll
        for (int i=0;i<4;i++) {
            int q = tid + i*256, k = q>>5, n4 = (q&31)*4;
            rb[i] = *(const float4*)(W + (size_t)(k0+k)*N + n0 + n4);
        }
    };
    auto sts = [&](int bb) {
        if (AP == 0) {
            __nv_bfloat16 *Ah = Ab(bb,0), *Al = Ab(bb,1);
            #pragma unroll
            for (int i=0;i<4;i++) {
                int q = tid + i*256, r = q>>3, c4 = (q&7)*4;
                float v[4] = {ra[i].x, ra[i].y, ra[i].z, ra[i].w};
                __nv_bfloat16 hh[4], ll[4];
                #pragma unroll
                for (int j=0;j<4;j++) split2(v[j], hh[j], ll[j]);
                *(__nv_bfloat162*)(Ah + r*40 + c4)   = __halves2bfloat162(hh[0],hh[1]);
                *(__nv_bfloat162*)(Ah + r*40 + c4+2) = __halves2bfloat162(hh[2],hh[3]);
                *(__nv_bfloat162*)(Al + r*40 + c4)   = __halves2bfloat162(ll[0],ll[1]);
                *(__nv_bfloat162*)(Al + r*40 + c4+2) = __halves2bfloat162(ll[2],ll[3]);
            }
        } else {
            #pragma unroll
            for (int i=0;i<4;i++) {
                int pl = i>>1, cid = tid + (i&1)*256, r = cid>>2, c = cid&3;
                *(uint4*)(Ab(bb,pl) + r*40 + c*8) = rua[i];
            }
        }
        __nv_bfloat16 *Bh = Bb(bb,0), *Bl = Bb(bb,1);
        #pragma unroll
        for (int i=0;i<4;i++) {
            int q = tid + i*256, k = q>>5, n4 = (q&31)*4;
            float v[4] = {rb[i].x, rb[i].y, rb[i].z, rb[i].w};
            __nv_bfloat16 hh[4], ll[4];
            #pragma unroll
            for (int j=0;j<4;j++) split2(v[j], hh[j], ll[j]);
            *(__nv_bfloat162*)(Bh + k*136 + n4)   = __halves2bfloat162(hh[0],hh[1]);
            *(__nv_bfloat162*)(Bh + k*136 + n4+2) = __halves2bfloat162(hh[2],hh[3]);
            *(__nv_bfloat162*)(Bl + k*136 + n4)   = __halves2bfloat162(ll[0],ll[1]);
            *(__nv_bfloat162*)(Bl + k*136 + n4+2) = __halves2bfloat162(ll[2],ll[3]);
        }
    };

    ldg(0); sts(0);
    __syncthreads();
    for (int c = 0; c < nc; c++) {
        int cur = c & 1;
        if (c + 1 < nc) ldg((c+1)*32);
        const __nv_bfloat16 *Ah=Ab(cur,0), *Al=Ab(cur,1), *Bh=Bb(cur,0), *Bl=Bb(cur,1);
        #pragma unroll
        for (int ks = 0; ks < 2; ks++) {
            FragAb ah[2], al[2];
            #pragma unroll
            for (int i=0;i<2;i++) {
                wmma::load_matrix_sync(ah[i], Ah + (wm*32+i*16)*40 + ks*16, 40);
                wmma::load_matrix_sync(al[i], Al + (wm*32+i*16)*40 + ks*16, 40);
            }
            #pragma unroll
            for (int n=0;n<4;n++) {
                FragBb bh, bl;
                wmma::load_matrix_sync(bh, Bh + (ks*16)*136 + wn*64 + n*16, 136);
                wmma::load_matrix_sync(bl, Bl + (ks*16)*136 + wn*64 + n*16, 136);
                #pragma unroll
                for (int i=0;i<2;i++) {
                    wmma::mma_sync(acc[i][n], ah[i], bh, acc[i][n]);
                    wmma::mma_sync(acc[i][n], al[i], bh, acc[i][n]);
                    wmma::mma_sync(acc[i][n], ah[i], bl, acc[i][n]);
                }
            }
        }
        if (c + 1 < nc) sts(cur ^ 1);
        __syncthreads();
    }
    float* Cs = (float*)smem;
    #pragma unroll
    for (int i=0;i<2;i++)
        #pragma unroll
        for (int n=0;n<4;n++)
            wmma::store_matrix_sync(Cs + (wm*32+i*16)*132 + wn*64 + n*16,
                                    acc[i][n], 132, wmma::mem_row_major);
    __syncthreads();
}

__global__ void __launch_bounds__(256,1) proj_in2(
    const float* A, const float* W1, const float* b1, float a1, __half* D1,
    const float* W2, const float* b2, float a2, __half* D2, int K, int lsh)
{
    extern __shared__ char smem[];
    const int tid = threadIdx.x;
    const int sel = blockIdx.x >> 2;
    const float* W = sel ? W2 : W1;
    const float* bias = sel ? b2 : b1;
    const float alpha = sel ? a2 : a1;
    __half* Dh = sel ? D2 : D1;
    const int m0 = blockIdx.y*128, n0 = (blockIdx.x & 3)*128;

    AccFrag acc[2][4];
    #pragma unroll
    for (int i=0;i<2;i++)
        #pragma unroll
        for (int n=0;n<4;n++) wmma::fill_fragment(acc[i][n], 0.0f);
    proj_main<0>(smem, A, 0, 0, W, K, 512, m0, n0, tid, acc);

    float* Cs = (float*)smem;
    const int Lm1 = (1 << lsh) - 1;
    for (int i = tid; i < 2048; i += 256) {
        int r = i>>4, c8 = (i&15)*8;
        int m = m0 + r, bb = m >> lsh, tok = m & Lm1;
        int n = n0 + c8, hh = n >> 6, d = n & 63;
        float x[8];
        #pragma unroll
        for (int j=0;j<8;j++)
            x[j] = alpha * (Cs[r*132 + c8 + j] + __ldg(bias + n + j));
        size_t o = (((size_t)(bb*H_ + hh) << lsh) + tok) * 64 + d;
        *(uint4*)(Dh + o) = pack8h(x);
    }
}

__global__ void __launch_bounds__(256,1) proj_out2(
    const float* W1, const float* b1, float* C1,
    const float* W2, const float* b2, float* C2)
{
    extern __shared__ char smem[];
    const int tid = threadIdx.x;
    const bool r2 = blockIdx.y >= 128;
    if (r2 && blockIdx.x >= 2) return;
    const int N = r2 ? 256 : 512;
    const int m0 = (r2 ? blockIdx.y - 128 : blockIdx.y) * 128;
    const int n0 = blockIdx.x * 128;
    const __nv_bfloat16* Aph = r2 ? g_oah : g_ovh;
    const __nv_bfloat16* Apl = r2 ? g_oal : g_ovl;
    const float* W = r2 ? W2 : W1;
    const float* bias = r2 ? b2 : b1;
    float* C = r2 ? C2 : C1;

    AccFrag acc[2][4];
    #pragma unroll
    for (int i=0;i<2;i++)
        #pragma unroll
        for (int n=0;n<4;n++) wmma::fill_fragment(acc[i][n], 0.0f);
    proj_main<1>(smem, 0, Aph, Apl, W, 512, N, m0, n0, tid, acc);

    float* Cs = (float*)smem;
    for (int i = tid; i < 4096; i += 256) {
        int r = i>>5, c4 = (i&31)*4;
        float4 v;
        v.x = Cs[r*132+c4+0] + __ldg(bias+n0+c4+0);
        v.y = Cs[r*132+c4+1] + __ldg(bias+n0+c4+1);
        v.z = Cs[r*132+c4+2] + __ldg(bias+n0+c4+2);
        v.w = Cs[r*132+c4+3] + __ldg(bias+n0+c4+3);
        *(float4*)(C + (size_t)(m0+r)*N + n0 + c4) = v;
    }
}

// ---------------------------------------------------------------------------
extern "C" void kernel_launch(void* const* d_in, const int* in_sizes, int n_in,
                              void* d_out, int out_size)
{
    const float* v    = (const float*)d_in[0];
    const float* a    = (const float*)d_in[1];
    const float* w_vq = (const float*)d_in[2];
    const float* b_vq = (const float*)d_in[3];
    const float* w_ak = (const float*)d_in[4];
    const float* b_ak = (const float*)d_in[5];
    const float* w_vv = (const float*)d_in[6];
    const float* b_vv = (const float*)d_in[7];
    const float* w_av = (const float*)d_in[8];
    const float* b_av = (const float*)d_in[9];
    const float* w_ov = (const float*)d_in[10];
    const float* b_ov = (const float*)d_in[11];
    const float* w_oa = (const float*)d_in[12];
    const float* b_oa = (const float*)d_in[13];
    float* out = (float*)d_out;

    __half *q, *k, *vv, *va;
    cudaGetSymbolAddress((void**)&q,  g_q);  cudaGetSymbolAddress((void**)&k,  g_k);
    cudaGetSymbolAddress((void**)&vv, g_vv); cudaGetSymbolAddress((void**)&va, g_va);

    cudaFuncSetAttribute(proj_in2,  cudaFuncAttributeMaxDynamicSharedMemorySize, PJSZ);
    cudaFuncSetAttribute(proj_out2, cudaFuncAttributeMaxDynamicSharedMemorySize, PJSZ);
    cudaFuncSetAttribute(scores_p,  cudaFuncAttributeMaxDynamicSharedMemorySize, SP_SZ);
    cudaFuncSetAttribute(gemm_outa, cudaFuncAttributeMaxDynamicSharedMemorySize, OA_SZ);
    cudaFuncSetAttribute(gemm_outv, cudaFuncAttributeMaxDynamicSharedMemorySize, FV_SZ);

    const float ALQ = 0.125f * 1.4426950408889634f;   // fold log2(e)
    proj_in2<<<dim3(8,128), 256, PJSZ>>>(v, w_vq, b_vq, ALQ, q,
                                         w_vv, b_vv, 1.0f, vv, VD_, 11);
    proj_in2<<<dim3(8,32), 256, PJSZ>>>(a, w_ak, b_ak, 1.0f, k,
                                        w_av, b_av, 1.0f, va, AD_, 9);

    scores_p <<<dim3(T_/128, S_/128, BH_), 256, SP_SZ>>>();
    gemm_outa<<<dim3(S_/128, BH_), 256, OA_SZ>>>();
    gemm_outv<<<dim3(T_/128, BH_), 256, FV_SZ>>>();

    proj_out2<<<dim3(4,160), 256, PJSZ>>>(w_ov, b_ov, out,
                                          w_oa, b_oa, out + (size_t)B_*T_*VD_);
}

// round 13
// speedup vs baseline: 1.3101x; 1.3101x over previous
#include <cuda_runtime.h>
#include <cuda_bf16.h>
#include <cuda_fp16.h>
#include <cstdint>

#define B_ 8
#define T_ 2048
#define S_ 512
#define VD_ 512
#define AD_ 256
#define E_ 512
#define H_ 8
#define BH_ 64

__device__ __half g_q [(size_t)BH_*T_*64];
__device__ __half g_k [(size_t)BH_*S_*64];
__device__ __half g_vv[(size_t)BH_*T_*64];
__device__ __half g_va[(size_t)BH_*S_*64];
__device__ __half g_v2[(size_t)BH_*S_*64];          // va / l
__device__ __half g_p [(size_t)BH_*S_*T_];          // exp2(S) fp16
__device__ __nv_bfloat16 g_ovh[(size_t)B_*T_*E_], g_ovl[(size_t)B_*T_*E_];
__device__ __nv_bfloat16 g_oah[(size_t)B_*S_*E_], g_oal[(size_t)B_*S_*E_];

__device__ __forceinline__ float ex2f(float x) {
    float r; asm("ex2.approx.f32 %0, %1;" : "=f"(r) : "f"(x)); return r;
}
__device__ __forceinline__ uint32_t cvta_s(const void* p) {
    uint32_t r;
    asm("{ .reg .u64 t; cvta.to.shared.u64 t, %1; cvt.u32.u64 %0, t; }" : "=r"(r) : "l"(p));
    return r;
}
__device__ __forceinline__ uint32_t h2u(float x, float y) {
    __half2 h = __floats2half2_rn(x, y); return *(uint32_t*)&h;
}
__device__ __forceinline__ void split2(float x, __nv_bfloat16& h, __nv_bfloat16& l) {
    h = __float2bfloat16(x);
    l = __float2bfloat16(x - __bfloat162float(h));
}
__device__ __forceinline__ void split8(const float* x, uint4& uh, uint4& ul) {
    union { __nv_bfloat16 b[8]; uint4 u; } Hh, Ll;
    #pragma unroll
    for (int j = 0; j < 8; j++) {
        __nv_bfloat16 hb = __float2bfloat16(x[j]);
        Hh.b[j] = hb; Ll.b[j] = __float2bfloat16(x[j] - __bfloat162float(hb));
    }
    uh = Hh.u; ul = Ll.u;
}
__device__ __forceinline__ uint4 pack8h(const float* x) {
    union { __half b[8]; uint4 u; } U;
    #pragma unroll
    for (int j = 0; j < 8; j++) U.b[j] = __float2half_rn(x[j]);
    return U.u;
}
__device__ __forceinline__ void ldsm4(uint32_t& r0, uint32_t& r1, uint32_t& r2, uint32_t& r3,
                                      uint32_t a) {
    asm volatile("ldmatrix.sync.aligned.m8n8.x4.shared.b16 {%0,%1,%2,%3}, [%4];"
                 : "=r"(r0), "=r"(r1), "=r"(r2), "=r"(r3) : "r"(a));
}
__device__ __forceinline__ void ldsm4t(uint32_t& r0, uint32_t& r1, uint32_t& r2, uint32_t& r3,
                                       uint32_t a) {
    asm volatile("ldmatrix.sync.aligned.m8n8.x4.trans.shared.b16 {%0,%1,%2,%3}, [%4];"
                 : "=r"(r0), "=r"(r1), "=r"(r2), "=r"(r3) : "r"(a));
}
// fp16 MMA (attention path)
__device__ __forceinline__ void mma4(float* c, const uint32_t* a, uint32_t b0, uint32_t b1) {
    asm volatile("mma.sync.aligned.m16n8k16.row.col.f32.f16.f16.f32 "
                 "{%0,%1,%2,%3}, {%4,%5,%6,%7}, {%8,%9}, {%0,%1,%2,%3};"
                 : "+f"(c[0]), "+f"(c[1]), "+f"(c[2]), "+f"(c[3])
                 : "r"(a[0]), "r"(a[1]), "r"(a[2]), "r"(a[3]), "r"(b0), "r"(b1));
}
// bf16 MMA (projection path) — R12's NaN was feeding bf16 data to the f16 MMA.
__device__ __forceinline__ void mma4b(float* c, const uint32_t* a, uint32_t b0, uint32_t b1) {
    asm volatile("mma.sync.aligned.m16n8k16.row.col.f32.bf16.bf16.f32 "
                 "{%0,%1,%2,%3}, {%4,%5,%6,%7}, {%8,%9}, {%0,%1,%2,%3};"
                 : "+f"(c[0]), "+f"(c[1]), "+f"(c[2]), "+f"(c[3])
                 : "r"(a[0]), "r"(a[1]), "r"(a[2]), "r"(a[3]), "r"(b0), "r"(b1));
}
#define CP16(dst, src) \
    asm volatile("cp.async.cg.shared.global [%0], [%1], 16;" :: "r"(dst), "l"(src))
#define CPCOMMIT() asm volatile("cp.async.commit_group;" ::: "memory")

// ============ scores_strip: P[s0:+128][all t] = exp2(K @ Q^T) ==============
#define SS_Q  36864
#define SS_SZ 92160

__global__ void __launch_bounds__(256,2) scores_strip()
{
    extern __shared__ char sm[];
    const uint32_t smb = cvta_s(sm);
    __half* PS = (__half*)sm;

    const int tid = threadIdx.x, w = tid>>5, lane = tid&31;
    const int gid = lane>>2, tig = lane&3, wq = lane&7;
    const int wm = w&3, wn = w>>2;
    const int bh = blockIdx.y;
    const int s0 = blockIdx.x*128;

    {   // K tile 128x64 -> smem (stride 72 halves)
        const uint4* ks = (const uint4*)(g_k + ((size_t)bh*S_+s0)*64);
        #pragma unroll
        for (int i = 0; i < 4; i++) {
            int q = tid + i*256, r = q>>3, c = q&7;
            *(uint4*)((__half*)sm + r*72 + c*8) = ks[q];
        }
    }
    __syncthreads();
    uint32_t KA[4][2][4];
    #pragma unroll
    for (int ksi = 0; ksi < 4; ksi++)
        #pragma unroll
        for (int i = 0; i < 2; i++) {
            uint32_t ad = smb + (uint32_t)(((wm*32+i*16+(lane&15))*72 + (lane>>4)*8)*2)
                        + ksi*32;
            ldsm4(KA[ksi][i][0], KA[ksi][i][1], KA[ksi][i][2], KA[ksi][i][3], ad);
        }
    __syncthreads();

    auto issueQ = [&](int it, int j) {
        const __half* qs = g_q + ((size_t)bh*T_ + it*128)*64;
        uint32_t base = smb + SS_Q + (uint32_t)(j*18432);
        #pragma unroll
        for (int i = 0; i < 4; i++) {
            int q = tid + i*256, r = q>>3, c = q&7;
            CP16(base + (uint32_t)(r*144 + c*16), qs + (size_t)r*64 + c*8);
        }
        CPCOMMIT();
    };
    issueQ(0, 0); issueQ(1, 1);

    const uint32_t qlo = (uint32_t)((wq + ((lane>>4)&1)*8)*144) + ((lane>>3)&1)*16;

    for (int it = 0; it < 16; it++) {
        if (it < 15) { asm volatile("cp.async.wait_group 1;" ::: "memory"); }
        else         { asm volatile("cp.async.wait_group 0;" ::: "memory"); }
        __syncthreads();
        if (it + 2 < 16) issueQ(it+2, (it+2)%3);

        const uint32_t qb = smb + SS_Q + (uint32_t)((it%3)*18432);
        float acc[2][8][4] = {};
        #pragma unroll
        for (int ksi = 0; ksi < 4; ksi++) {
            #pragma unroll
            for (int jb = 0; jb < 4; jb++) {
                uint32_t q0,q1,q2,q3;
                ldsm4(q0,q1,q2,q3, qb + qlo + (wn*64 + jb*16)*144 + ksi*32);
                #pragma unroll
                for (int i = 0; i < 2; i++) {
                    mma4(acc[i][jb*2],   KA[ksi][i], q0, q1);
                    mma4(acc[i][jb*2+1], KA[ksi][i], q2, q3);
                }
            }
        }
        #pragma unroll
        for (int i = 0; i < 2; i++)
            #pragma unroll
            for (int nf = 0; nf < 8; nf++) {
                int col = wn*64 + nf*8 + 2*tig;
                int r0 = wm*32 + i*16 + gid;
                *(uint32_t*)(PS + r0*136 + col) =
                    h2u(ex2f(acc[i][nf][0]), ex2f(acc[i][nf][1]));
                *(uint32_t*)(PS + (r0+8)*136 + col) =
                    h2u(ex2f(acc[i][nf][2]), ex2f(acc[i][nf][3]));
            }
        __syncthreads();
        {
            int r = tid>>1, c0 = (tid&1)*64;
            const __half* ps = PS + r*136 + c0;
            __half* gp = g_p + ((size_t)(bh*S_+s0+r))*T_ + it*128 + c0;
            #pragma unroll
            for (int i = 0; i < 8; i++)
                *(uint4*)(gp + i*8) = *(const uint4*)(ps + i*8);
        }
        __syncthreads();
    }
}

// ============ gemm_outa: out_a = (P @ vv)/l ; va2 = va/l ===================
#define OA_VB 30720
#define OA_LS 45056
#define OA_SZ 45568

__global__ void __launch_bounds__(256,2) gemm_outa()
{
    extern __shared__ char sm[];
    const uint32_t smb = cvta_s(sm);
    float* lsm = (float*)(sm + OA_LS);
    float* OS  = (float*)sm;

    const int tid = threadIdx.x, w = tid>>5, lane = tid&31;
    const int wm = w&3, wn = w>>2;
    const int gid = lane>>2, tig = lane&3, wq = lane&7;
    const int bh = blockIdx.y, b = bh>>3, h = bh&7;
    const int s0 = blockIdx.x*128;

    const int pr = tid>>1, pc = (tid&1)*16;
    const __half* psrc = g_p + (size_t)(bh*S_ + s0 + pr)*T_ + pc;
    const uint32_t pdst = smb + (uint32_t)(pr*80 + pc*2);
    const int vr = tid>>3, vc = tid&7;
    const __half* vsrc = g_vv + (size_t)bh*T_*64 + (size_t)vr*64 + vc*8;
    const uint32_t vdst = smb + OA_VB + (uint32_t)(vr*144 + vc*16);

    #pragma unroll
    for (int c = 0; c < 2; c++) {
        CP16(pdst + c*10240,      psrc + (size_t)c*32);
        CP16(pdst + c*10240 + 16, psrc + (size_t)c*32 + 8);
        CP16(vdst + c*4608,       vsrc + (size_t)c*32*64);
        CPCOMMIT();
    }

    float acc[2][4][4] = {};
    float lr[2][2] = {};

    for (int c = 0; c < 64; c++) {
        if (c < 63) { asm volatile("cp.async.wait_group 1;" ::: "memory"); }
        else        { asm volatile("cp.async.wait_group 0;" ::: "memory"); }
        __syncthreads();
        if (c + 2 < 64) {
            int j = (c+2)%3;
            CP16(pdst + j*10240,      psrc + (size_t)(c+2)*32);
            CP16(pdst + j*10240 + 16, psrc + (size_t)(c+2)*32 + 8);
            CP16(vdst + j*4608,       vsrc + (size_t)(c+2)*32*64);
            CPCOMMIT();
        }
        const uint32_t pb = smb + (uint32_t)((c%3)*10240);
        const uint32_t vb = smb + OA_VB + (uint32_t)((c%3)*4608);
        #pragma unroll
        for (int ks = 0; ks < 2; ks++) {
            uint32_t aa[2][4];
            #pragma unroll
            for (int i = 0; i < 2; i++) {
                uint32_t ad = pb + (uint32_t)(((wm*32+i*16+(lane&15))*40
                             + ks*16 + (lane>>4)*8)*2);
                ldsm4(aa[i][0], aa[i][1], aa[i][2], aa[i][3], ad);
                if (wn == 0) {
                    float2 f0 = __half22float2(*(__half2*)&aa[i][0]);
                    float2 f2 = __half22float2(*(__half2*)&aa[i][2]);
                    float2 f1 = __half22float2(*(__half2*)&aa[i][1]);
                    float2 f3 = __half22float2(*(__half2*)&aa[i][3]);
                    lr[i][0] += f0.x+f0.y+f2.x+f2.y;
                    lr[i][1] += f1.x+f1.y+f3.x+f3.y;
                }
            }
            #pragma unroll
            for (int jn = 0; jn < 2; jn++) {
                uint32_t v0,v1,v2,v3;
                uint32_t bd = vb + (uint32_t)((ks*16 + wq + ((lane>>3)&1)*8)*144)
                            + (uint32_t)((wn*32 + jn*16)*2) + ((lane>>4)&1)*16;
                ldsm4t(v0,v1,v2,v3, bd);
                #pragma unroll
                for (int i = 0; i < 2; i++) {
                    mma4(acc[i][2*jn],   aa[i], v0, v1);
                    mma4(acc[i][2*jn+1], aa[i], v2, v3);
                }
            }
        }
        __syncthreads();
    }

    #pragma unroll
    for (int i = 0; i < 2; i++)
        #pragma unroll
        for (int hh2 = 0; hh2 < 2; hh2++) {
            lr[i][hh2] += __shfl_xor_sync(0xffffffffu, lr[i][hh2], 1);
            lr[i][hh2] += __shfl_xor_sync(0xffffffffu, lr[i][hh2], 2);
        }
    if (wn == 0 && tig == 0) {
        #pragma unroll
        for (int i = 0; i < 2; i++) {
            lsm[wm*32 + i*16 + gid]     = lr[i][0];
            lsm[wm*32 + i*16 + gid + 8] = lr[i][1];
        }
    }
    __syncthreads();
    {
        #pragma unroll
        for (int i = 0; i < 2; i++) {
            int r0 = wm*32 + i*16 + gid;
            float inv0 = 1.0f/lsm[r0], inv1 = 1.0f/lsm[r0+8];
            #pragma unroll
            for (int nf = 0; nf < 4; nf++) {
                int cb = wn*32 + nf*8 + 2*tig;
                OS[r0*68 + cb]       = acc[i][nf][0]*inv0;
                OS[r0*68 + cb + 1]   = acc[i][nf][1]*inv0;
                OS[(r0+8)*68 + cb]   = acc[i][nf][2]*inv1;
                OS[(r0+8)*68 + cb+1] = acc[i][nf][3]*inv1;
            }
        }
    }
    __syncthreads();
    {
        int r = tid>>1, c0 = (tid&1)*32;
        float inv = 1.0f/lsm[r];
        float x[32];
        const float* row = OS + r*68 + c0;
        #pragma unroll
        for (int g4 = 0; g4 < 8; g4++) *(float4*)(x+g4*4) = *(const float4*)(row+g4*4);
        size_t o = ((size_t)(b*S_+s0+r))*E_ + h*64 + c0;
        #pragma unroll
        for (int g8 = 0; g8 < 4; g8++) {
            uint4 uh, ul; split8(x+g8*8, uh, ul);
            *(uint4*)(g_oah+o+g8*8) = uh; *(uint4*)(g_oal+o+g8*8) = ul;
        }
        size_t vi = ((size_t)(bh*S_+s0+r))*64 + c0;
        #pragma unroll
        for (int g8 = 0; g8 < 4; g8++) {
            uint4 wv = *(uint4*)(g_va + vi + g8*8);
            const __half* hp = (const __half*)&wv;
            float y[8];
            #pragma unroll
            for (int j = 0; j < 8; j++) y[j] = __half2float(hp[j]) * inv;
            *(uint4*)(g_v2 + vi + g8*8) = pack8h(y);
        }
    }
}

// ============ gemm_outv: out_v = P^T @ va2 (K=512) =========================
#define FV_AB 26112
#define FV_SZ 39936

__global__ void __launch_bounds__(256,2) gemm_outv()
{
    extern __shared__ char sm[];
    const uint32_t smb = cvta_s(sm);
    float* OS = (float*)sm;

    const int tid = threadIdx.x, w = tid>>5, lane = tid&31;
    const int wm = w&3, wn = w>>2;
    const int gid = lane>>2, tig = lane&3;
    const int bh = blockIdx.y, b = bh>>3, h = bh&7;
    const int t0 = blockIdx.x*128;

    const int cr = tid>>3, cc = tid&7;
    const __half* psrc = g_p  + (size_t)(bh*S_ + cr)*T_ + t0 + cc*8;
    const __half* asrc = g_v2 + (size_t)(bh*S_ + cr)*64 + cc*8;
    const uint32_t pdst = smb + (uint32_t)(cr*272 + cc*16);
    const uint32_t adst = smb + FV_AB + (uint32_t)(cr*144 + cc*16);

    #pragma unroll
    for (int c = 0; c < 2; c++) {
        CP16(pdst + c*8704,       psrc + (size_t)c*32*T_);
        CP16(pdst + c*8704 + 128, psrc + (size_t)c*32*T_ + 64);
        CP16(adst + c*4608,       asrc + (size_t)c*32*64);
        CPCOMMIT();
    }

    float acc[2][4][4] = {};

    for (int c = 0; c < 16; c++) {
        if (c < 15) { asm volatile("cp.async.wait_group 1;" ::: "memory"); }
        else        { asm volatile("cp.async.wait_group 0;" ::: "memory"); }
        __syncthreads();
        if (c + 2 < 16) {
            int j = (c+2)%3;
            CP16(pdst + j*8704,       psrc + (size_t)(c+2)*32*T_);
            CP16(pdst + j*8704 + 128, psrc + (size_t)(c+2)*32*T_ + 64);
            CP16(adst + j*4608,       asrc + (size_t)(c+2)*32*64);
            CPCOMMIT();
        }
        const uint32_t pb = smb + (uint32_t)((c%3)*8704);
        const uint32_t ab = smb + FV_AB + (uint32_t)((c%3)*4608);
        #pragma unroll
        for (int ks = 0; ks < 2; ks++) {
            uint32_t aa[2][4];
            #pragma unroll
            for (int i = 0; i < 2; i++) {
                uint32_t ad = pb + (uint32_t)(((ks*16 + (lane&7) + ((lane>>4)&1)*8)*136
                              + wm*32 + i*16 + ((lane>>3)&1)*8)*2);
                ldsm4t(aa[i][0], aa[i][1], aa[i][2], aa[i][3], ad);
            }
            #pragma unroll
            for (int jn = 0; jn < 2; jn++) {
                uint32_t v0,v1,v2,v3;
                uint32_t bd = ab + (uint32_t)(((ks*16 + (lane&7) + ((lane>>3)&1)*8)*72
                              + wn*32 + jn*16 + ((lane>>4)&1)*8)*2);
                ldsm4t(v0,v1,v2,v3, bd);
                #pragma unroll
                for (int i = 0; i < 2; i++) {
                    mma4(acc[i][2*jn],   aa[i], v0, v1);
                    mma4(acc[i][2*jn+1], aa[i], v2, v3);
                }
            }
        }
        __syncthreads();
    }
    {
        #pragma unroll
        for (int i = 0; i < 2; i++)
            #pragma unroll
            for (int nf = 0; nf < 4; nf++) {
                int rr = wm*32 + i*16 + gid, cbase = wn*32 + nf*8 + 2*tig;
                OS[rr*68 + cbase]       = acc[i][nf][0];
                OS[rr*68 + cbase + 1]   = acc[i][nf][1];
                OS[(rr+8)*68 + cbase]   = acc[i][nf][2];
                OS[(rr+8)*68 + cbase+1] = acc[i][nf][3];
            }
    }
    __syncthreads();
    {
        int r = tid>>1, c0 = (tid&1)*32;
        float x[32];
        const float* row = OS + r*68 + c0;
        #pragma unroll
        for (int g4 = 0; g4 < 8; g4++) *(float4*)(x+g4*4) = *(const float4*)(row+g4*4);
        size_t o = ((size_t)(b*T_+t0+r))*E_ + h*64 + c0;
        #pragma unroll
        for (int g8 = 0; g8 < 4; g8++) {
            uint4 uh, ul; split8(x+g8*8, uh, ul);
            *(uint4*)(g_ovh+o+g8*8) = uh; *(uint4*)(g_ovl+o+g8*8) = ul;
        }
    }
}

// ============ raw-mma projection (128x128 tile, KC=32, 3-term bf16) ========
#define PJ_B   20480
#define PJ_SZ  37888

template<int AP, int OP>
__device__ __forceinline__ void proj_body(
    const float* A, const __nv_bfloat16* Aph, const __nv_bfloat16* Apl,
    const float* W, const float* bias, float* C, __half* Dh,
    int K, int N, int m0, int n0, float alpha, int lsh)
{
    extern __shared__ char sm[];
    const uint32_t smb = cvta_s(sm);
    const int tid = threadIdx.x, w = tid>>5, lane = tid&31;
    const int wm = w&3, wn = w>>2;
    const int gid = lane>>2, tig = lane&3, wq = lane&7;

    float acc[2][8][4] = {};
    const int nc = K >> 5;

    for (int c = 0; c < nc; c++) {
        const int k0 = c*32;
        __syncthreads();
        if (AP == 0) {
            #pragma unroll
            for (int i = 0; i < 4; i++) {
                int q = tid + i*256, r = q>>3, c4 = (q&7)*4;
                float4 v = *(const float4*)(A + (size_t)(m0+r)*K + k0 + c4);
                float xx[4] = {v.x, v.y, v.z, v.w};
                __nv_bfloat16 hh[4], ll[4];
                #pragma unroll
                for (int j = 0; j < 4; j++) split2(xx[j], hh[j], ll[j]);
                __nv_bfloat16* Ah = (__nv_bfloat16*)sm + r*40 + c4;
                *(__nv_bfloat162*)Ah       = __halves2bfloat162(hh[0],hh[1]);
                *(__nv_bfloat162*)(Ah+2)   = __halves2bfloat162(hh[2],hh[3]);
                __nv_bfloat16* Al = (__nv_bfloat16*)(sm+10240) + r*40 + c4;
                *(__nv_bfloat162*)Al       = __halves2bfloat162(ll[0],ll[1]);
                *(__nv_bfloat162*)(Al+2)   = __halves2bfloat162(ll[2],ll[3]);
            }
        } else {
            #pragma unroll
            for (int i = 0; i < 4; i++) {
                int pl = i>>1, cid = tid + (i&1)*256, r = cid>>2, cc = cid&3;
                const __nv_bfloat16* src = (pl ? Apl : Aph) + (size_t)(m0+r)*K + k0;
                uint4 u = ((const uint4*)src)[cc];
                *(uint4*)((__nv_bfloat16*)(sm + pl*10240) + r*40 + cc*8) = u;
            }
        }
        #pragma unroll
        for (int i = 0; i < 4; i++) {
            int q = tid + i*256, k = q>>5, n4 = (q&31)*4;
            float4 v = *(const float4*)(W + (size_t)(k0+k)*N + n0 + n4);
            float xx[4] = {v.x, v.y, v.z, v.w};
            __nv_bfloat16 hh[4], ll[4];
            #pragma unroll
            for (int j = 0; j < 4; j++) split2(xx[j], hh[j], ll[j]);
            __nv_bfloat16* Bh = (__nv_bfloat16*)(sm + PJ_B) + k*136 + n4;
            *(__nv_bfloat162*)Bh     = __halves2bfloat162(hh[0],hh[1]);
            *(__nv_bfloat162*)(Bh+2) = __halves2bfloat162(hh[2],hh[3]);
            __nv_bfloat16* Bl = (__nv_bfloat16*)(sm + PJ_B + 8704) + k*136 + n4;
            *(__nv_bfloat162*)Bl     = __halves2bfloat162(ll[0],ll[1]);
            *(__nv_bfloat162*)(Bl+2) = __halves2bfloat162(ll[2],ll[3]);
        }
        __syncthreads();
        #pragma unroll
        for (int ks = 0; ks < 2; ks++) {
            uint32_t ah[2][4], al[2][4];
            #pragma unroll
            for (int i = 0; i < 2; i++) {
                uint32_t ad = smb + (uint32_t)(((wm*32+i*16+(lane&15))*40
                             + ks*16 + (lane>>4)*8)*2);
                ldsm4(ah[i][0], ah[i][1], ah[i][2], ah[i][3], ad);
                ldsm4(al[i][0], al[i][1], al[i][2], al[i][3], ad + 10240);
            }
            #pragma unroll
            for (int g = 0; g < 4; g++) {
                uint32_t bdH = smb + PJ_B
                    + (uint32_t)((ks*16 + wq + ((lane>>3)&1)*8)*272)
                    + (uint32_t)((wn*64 + g*16)*2) + ((lane>>4)&1)*16;
                uint32_t b0,b1,b2,b3, l0,l1,l2,l3;
                ldsm4t(b0,b1,b2,b3, bdH);
                ldsm4t(l0,l1,l2,l3, bdH + 8704);
                #pragma unroll
                for (int i = 0; i < 2; i++) {
                    mma4b(acc[i][2*g],   ah[i], b0, b1);
                    mma4b(acc[i][2*g+1], ah[i], b2, b3);
                    mma4b(acc[i][2*g],   al[i], b0, b1);
                    mma4b(acc[i][2*g+1], al[i], b2, b3);
                    mma4b(acc[i][2*g],   ah[i], l0, l1);
                    mma4b(acc[i][2*g+1], ah[i], l2, l3);
                }
            }
        }
    }

    float* OS = (float*)sm;
    #pragma unroll
    for (int hf = 0; hf < 2; hf++) {
        __syncthreads();
        if (wn == hf) {
            #pragma unroll
            for (int i = 0; i < 2; i++)
                #pragma unroll
                for (int nf = 0; nf < 8; nf++) {
                    int r0 = wm*32 + i*16 + gid, cb = nf*8 + 2*tig;
                    OS[r0*68 + cb]       = acc[i][nf][0];
                    OS[r0*68 + cb + 1]   = acc[i][nf][1];
                    OS[(r0+8)*68 + cb]   = acc[i][nf][2];
                    OS[(r0+8)*68 + cb+1] = acc[i][nf][3];
                }
        }
        __syncthreads();
        const int r = tid>>1, c0 = (tid&1)*32;
        const int nbase = n0 + hf*64;
        if (OP == 0) {
            const int Lm1 = (1 << lsh) - 1;
            int m = m0 + r, bb = m >> lsh, tok = m & Lm1;
            int hh = nbase >> 6;
            size_t o = (((size_t)(bb*H_ + hh) << lsh) + tok) * 64 + c0;
            #pragma unroll
            for (int g8 = 0; g8 < 4; g8++) {
                float x[8];
                #pragma unroll
                for (int j = 0; j < 8; j++)
                    x[j] = alpha * (OS[r*68 + c0 + g8*8 + j]
                                    + __ldg(bias + nbase + c0 + g8*8 + j));
                *(uint4*)(Dh + o + g8*8) = pack8h(x);
            }
        } else {
            float* crow = C + (size_t)(m0+r)*N + nbase + c0;
            #pragma unroll
            for (int g4 = 0; g4 < 8; g4++) {
                float4 v;
                v.x = OS[r*68 + c0 + g4*4 + 0] + __ldg(bias + nbase + c0 + g4*4 + 0);
                v.y = OS[r*68 + c0 + g4*4 + 1] + __ldg(bias + nbase + c0 + g4*4 + 1);
                v.z = OS[r*68 + c0 + g4*4 + 2] + __ldg(bias + nbase + c0 + g4*4 + 2);
                v.w = OS[r*68 + c0 + g4*4 + 3] + __ldg(bias + nbase + c0 + g4*4 + 3);
                *(float4*)(crow + g4*4) = v;
            }
        }
    }
}

__global__ void __launch_bounds__(256,2) proj_in2(
    const float* A, const float* W1, const float* b1, float a1, __half* D1,
    const float* W2, const float* b2, float a2, __half* D2, int K, int lsh)
{
    const int sel = blockIdx.x >> 2;
    proj_body<0,0>(A, 0, 0,
                   sel ? W2 : W1, sel ? b2 : b1, 0, sel ? D2 : D1,
                   K, 512, blockIdx.y*128, (blockIdx.x & 3)*128,
                   sel ? a2 : a1, lsh);
}

__global__ void __launch_bounds__(256,2) proj_out2(
    const float* W1, const float* b1, float* C1,
    const float* W2, const float* b2, float* C2)
{
    const bool r2 = blockIdx.y >= 128;
    if (r2 && blockIdx.x >= 2) return;
    proj_body<1,1>(0, r2 ? g_oah : g_ovh, r2 ? g_oal : g_ovl,
                   r2 ? W2 : W1, r2 ? b2 : b1, r2 ? C2 : C1, 0,
                   512, r2 ? 256 : 512,
                   (r2 ? blockIdx.y - 128 : blockIdx.y)*128, blockIdx.x*128,
                   1.0f, 0);
}

// ---------------------------------------------------------------------------
extern "C" void kernel_launch(void* const* d_in, const int* in_sizes, int n_in,
                              void* d_out, int out_size)
{
    const float* v    = (const float*)d_in[0];
    const float* a    = (const float*)d_in[1];
    const float* w_vq = (const float*)d_in[2];
    const float* b_vq = (const float*)d_in[3];
    const float* w_ak = (const float*)d_in[4];
    const float* b_ak = (const float*)d_in[5];
    const float* w_vv = (const float*)d_in[6];
    const float* b_vv = (const float*)d_in[7];
    const float* w_av = (const float*)d_in[8];
    const float* b_av = (const float*)d_in[9];
    const float* w_ov = (const float*)d_in[10];
    const float* b_ov = (const float*)d_in[11];
    const float* w_oa = (const float*)d_in[12];
    const float* b_oa = (const float*)d_in[13];
    float* out = (float*)d_out;

    __half *q, *k, *vv, *va;
    cudaGetSymbolAddress((void**)&q,  g_q);  cudaGetSymbolAddress((void**)&k,  g_k);
    cudaGetSymbolAddress((void**)&vv, g_vv); cudaGetSymbolAddress((void**)&va, g_va);

    cudaFuncSetAttribute(proj_in2,  cudaFuncAttributeMaxDynamicSharedMemorySize, PJ_SZ);
    cudaFuncSetAttribute(proj_out2, cudaFuncAttributeMaxDynamicSharedMemorySize, PJ_SZ);
    cudaFuncSetAttribute(scores_strip, cudaFuncAttributeMaxDynamicSharedMemorySize, SS_SZ);
    cudaFuncSetAttribute(gemm_outa, cudaFuncAttributeMaxDynamicSharedMemorySize, OA_SZ);
    cudaFuncSetAttribute(gemm_outv, cudaFuncAttributeMaxDynamicSharedMemorySize, FV_SZ);

    const float ALQ = 0.125f * 1.4426950408889634f;   // fold log2(e)
    proj_in2<<<dim3(8,128), 256, PJ_SZ>>>(v, w_vq, b_vq, ALQ, q,
                                          w_vv, b_vv, 1.0f, vv, VD_, 11);
    proj_in2<<<dim3(8,32), 256, PJ_SZ>>>(a, w_ak, b_ak, 1.0f, k,
                                         w_av, b_av, 1.0f, va, AD_, 9);

    scores_strip<<<dim3(4, BH_), 256, SS_SZ>>>();
    gemm_outa<<<dim3(S_/128, BH_), 256, OA_SZ>>>();
    gemm_outv<<<dim3(T_/128, BH_), 256, FV_SZ>>>();

    proj_out2<<<dim3(4,160), 256, PJ_SZ>>>(w_ov, b_ov, out,
                                           w_oa, b_oa, out + (size_t)B_*T_*VD_);
}

// round 14
// speedup vs baseline: 1.6263x; 1.2414x over previous
#include <cuda_runtime.h>
#include <cuda_fp16.h>
#include <cstdint>

#define B_ 8
#define T_ 2048
#define S_ 512
#define VD_ 512
#define AD_ 256
#define E_ 512
#define H_ 8
#define BH_ 64

__device__ __half g_q [(size_t)BH_*T_*64];
__device__ __half g_k [(size_t)BH_*S_*64];
__device__ __half g_vv[(size_t)BH_*T_*64];
__device__ __half g_va[(size_t)BH_*S_*64];
__device__ __half g_v2[(size_t)BH_*S_*64];          // va / l
__device__ __half g_p [(size_t)BH_*S_*T_];          // exp2(S) fp16
__device__ __half g_ov[(size_t)B_*T_*E_];           // attention out (visual), fp16
__device__ __half g_oa[(size_t)B_*S_*E_];           // attention out (audio),  fp16

__device__ __forceinline__ float ex2f(float x) {
    float r; asm("ex2.approx.f32 %0, %1;" : "=f"(r) : "f"(x)); return r;
}
__device__ __forceinline__ uint32_t cvta_s(const void* p) {
    uint32_t r;
    asm("{ .reg .u64 t; cvta.to.shared.u64 t, %1; cvt.u32.u64 %0, t; }" : "=r"(r) : "l"(p));
    return r;
}
__device__ __forceinline__ uint32_t h2u(float x, float y) {
    __half2 h = __floats2half2_rn(x, y); return *(uint32_t*)&h;
}
__device__ __forceinline__ uint2 pack4h(float a, float b, float c, float d) {
    __half2 h0 = __floats2half2_rn(a, b), h1 = __floats2half2_rn(c, d);
    return make_uint2(*(uint32_t*)&h0, *(uint32_t*)&h1);
}
__device__ __forceinline__ uint4 pack8h(const float* x) {
    union { __half b[8]; uint4 u; } U;
    #pragma unroll
    for (int j = 0; j < 8; j++) U.b[j] = __float2half_rn(x[j]);
    return U.u;
}
__device__ __forceinline__ void ldsm4(uint32_t& r0, uint32_t& r1, uint32_t& r2, uint32_t& r3,
                                      uint32_t a) {
    asm volatile("ldmatrix.sync.aligned.m8n8.x4.shared.b16 {%0,%1,%2,%3}, [%4];"
                 : "=r"(r0), "=r"(r1), "=r"(r2), "=r"(r3) : "r"(a));
}
__device__ __forceinline__ void ldsm4t(uint32_t& r0, uint32_t& r1, uint32_t& r2, uint32_t& r3,
                                       uint32_t a) {
    asm volatile("ldmatrix.sync.aligned.m8n8.x4.trans.shared.b16 {%0,%1,%2,%3}, [%4];"
                 : "=r"(r0), "=r"(r1), "=r"(r2), "=r"(r3) : "r"(a));
}
__device__ __forceinline__ void mma4(float* c, const uint32_t* a, uint32_t b0, uint32_t b1) {
    asm volatile("mma.sync.aligned.m16n8k16.row.col.f32.f16.f16.f32 "
                 "{%0,%1,%2,%3}, {%4,%5,%6,%7}, {%8,%9}, {%0,%1,%2,%3};"
                 : "+f"(c[0]), "+f"(c[1]), "+f"(c[2]), "+f"(c[3])
                 : "r"(a[0]), "r"(a[1]), "r"(a[2]), "r"(a[3]), "r"(b0), "r"(b1));
}
#define CP16(dst, src) \
    asm volatile("cp.async.cg.shared.global [%0], [%1], 16;" :: "r"(dst), "l"(src))
#define CPCOMMIT() asm volatile("cp.async.commit_group;" ::: "memory")

// ============ scores_strip: P[s0:+128][all t] = exp2(K @ Q^T) ==============
#define SS_Q  36864
#define SS_SZ 92160

__global__ void __launch_bounds__(256,2) scores_strip()
{
    extern __shared__ char sm[];
    const uint32_t smb = cvta_s(sm);
    __half* PS = (__half*)sm;

    const int tid = threadIdx.x, w = tid>>5, lane = tid&31;
    const int gid = lane>>2, tig = lane&3, wq = lane&7;
    const int wm = w&3, wn = w>>2;
    const int bh = blockIdx.y;
    const int s0 = blockIdx.x*128;

    {   // K tile 128x64 -> smem (stride 72 halves)
        const uint4* ks = (const uint4*)(g_k + ((size_t)bh*S_+s0)*64);
        #pragma unroll
        for (int i = 0; i < 4; i++) {
            int q = tid + i*256, r = q>>3, c = q&7;
            *(uint4*)((__half*)sm + r*72 + c*8) = ks[q];
        }
    }
    __syncthreads();
    uint32_t KA[4][2][4];
    #pragma unroll
    for (int ksi = 0; ksi < 4; ksi++)
        #pragma unroll
        for (int i = 0; i < 2; i++) {
            uint32_t ad = smb + (uint32_t)(((wm*32+i*16+(lane&15))*72 + (lane>>4)*8)*2)
                        + ksi*32;
            ldsm4(KA[ksi][i][0], KA[ksi][i][1], KA[ksi][i][2], KA[ksi][i][3], ad);
        }
    __syncthreads();

    auto issueQ = [&](int it, int j) {
        const __half* qs = g_q + ((size_t)bh*T_ + it*128)*64;
        uint32_t base = smb + SS_Q + (uint32_t)(j*18432);
        #pragma unroll
        for (int i = 0; i < 4; i++) {
            int q = tid + i*256, r = q>>3, c = q&7;
            CP16(base + (uint32_t)(r*144 + c*16), qs + (size_t)r*64 + c*8);
        }
        CPCOMMIT();
    };
    issueQ(0, 0); issueQ(1, 1);

    const uint32_t qlo = (uint32_t)((wq + ((lane>>4)&1)*8)*144) + ((lane>>3)&1)*16;

    for (int it = 0; it < 16; it++) {
        if (it < 15) { asm volatile("cp.async.wait_group 1;" ::: "memory"); }
        else         { asm volatile("cp.async.wait_group 0;" ::: "memory"); }
        __syncthreads();
        if (it + 2 < 16) issueQ(it+2, (it+2)%3);

        const uint32_t qb = smb + SS_Q + (uint32_t)((it%3)*18432);
        float acc[2][8][4] = {};
        #pragma unroll
        for (int ksi = 0; ksi < 4; ksi++) {
            #pragma unroll
            for (int jb = 0; jb < 4; jb++) {
                uint32_t q0,q1,q2,q3;
                ldsm4(q0,q1,q2,q3, qb + qlo + (wn*64 + jb*16)*144 + ksi*32);
                #pragma unroll
                for (int i = 0; i < 2; i++) {
                    mma4(acc[i][jb*2],   KA[ksi][i], q0, q1);
                    mma4(acc[i][jb*2+1], KA[ksi][i], q2, q3);
                }
            }
        }
        #pragma unroll
        for (int i = 0; i < 2; i++)
            #pragma unroll
            for (int nf = 0; nf < 8; nf++) {
                int col = wn*64 + nf*8 + 2*tig;
                int r0 = wm*32 + i*16 + gid;
                *(uint32_t*)(PS + r0*136 + col) =
                    h2u(ex2f(acc[i][nf][0]), ex2f(acc[i][nf][1]));
                *(uint32_t*)(PS + (r0+8)*136 + col) =
                    h2u(ex2f(acc[i][nf][2]), ex2f(acc[i][nf][3]));
            }
        __syncthreads();
        {
            int r = tid>>1, c0 = (tid&1)*64;
            const __half* ps = PS + r*136 + c0;
            __half* gp = g_p + ((size_t)(bh*S_+s0+r))*T_ + it*128 + c0;
            #pragma unroll
            for (int i = 0; i < 8; i++)
                *(uint4*)(gp + i*8) = *(const uint4*)(ps + i*8);
        }
        __syncthreads();
    }
}

// ============ gemm_outa: out_a = (P @ vv)/l ; va2 = va/l ===================
#define OA_VB 30720
#define OA_LS 45056
#define OA_SZ 45568

__global__ void __launch_bounds__(256,2) gemm_outa()
{
    extern __shared__ char sm[];
    const uint32_t smb = cvta_s(sm);
    float* lsm = (float*)(sm + OA_LS);
    float* OS  = (float*)sm;

    const int tid = threadIdx.x, w = tid>>5, lane = tid&31;
    const int wm = w&3, wn = w>>2;
    const int gid = lane>>2, tig = lane&3, wq = lane&7;
    const int bh = blockIdx.y, b = bh>>3, h = bh&7;
    const int s0 = blockIdx.x*128;

    const int pr = tid>>1, pc = (tid&1)*16;
    const __half* psrc = g_p + (size_t)(bh*S_ + s0 + pr)*T_ + pc;
    const uint32_t pdst = smb + (uint32_t)(pr*80 + pc*2);
    const int vr = tid>>3, vc = tid&7;
    const __half* vsrc = g_vv + (size_t)bh*T_*64 + (size_t)vr*64 + vc*8;
    const uint32_t vdst = smb + OA_VB + (uint32_t)(vr*144 + vc*16);

    #pragma unroll
    for (int c = 0; c < 2; c++) {
        CP16(pdst + c*10240,      psrc + (size_t)c*32);
        CP16(pdst + c*10240 + 16, psrc + (size_t)c*32 + 8);
        CP16(vdst + c*4608,       vsrc + (size_t)c*32*64);
        CPCOMMIT();
    }

    float acc[2][4][4] = {};
    float lr[2][2] = {};

    for (int c = 0; c < 64; c++) {
        if (c < 63) { asm volatile("cp.async.wait_group 1;" ::: "memory"); }
        else        { asm volatile("cp.async.wait_group 0;" ::: "memory"); }
        __syncthreads();
        if (c + 2 < 64) {
            int j = (c+2)%3;
            CP16(pdst + j*10240,      psrc + (size_t)(c+2)*32);
            CP16(pdst + j*10240 + 16, psrc + (size_t)(c+2)*32 + 8);
            CP16(vdst + j*4608,       vsrc + (size_t)(c+2)*32*64);
            CPCOMMIT();
        }
        const uint32_t pb = smb + (uint32_t)((c%3)*10240);
        const uint32_t vb = smb + OA_VB + (uint32_t)((c%3)*4608);
        #pragma unroll
        for (int ks = 0; ks < 2; ks++) {
            uint32_t aa[2][4];
            #pragma unroll
            for (int i = 0; i < 2; i++) {
                uint32_t ad = pb + (uint32_t)(((wm*32+i*16+(lane&15))*40
                             + ks*16 + (lane>>4)*8)*2);
                ldsm4(aa[i][0], aa[i][1], aa[i][2], aa[i][3], ad);
                if (wn == 0) {
                    float2 f0 = __half22float2(*(__half2*)&aa[i][0]);
                    float2 f2 = __half22float2(*(__half2*)&aa[i][2]);
                    float2 f1 = __half22float2(*(__half2*)&aa[i][1]);
                    float2 f3 = __half22float2(*(__half2*)&aa[i][3]);
                    lr[i][0] += f0.x+f0.y+f2.x+f2.y;
                    lr[i][1] += f1.x+f1.y+f3.x+f3.y;
                }
            }
            #pragma unroll
            for (int jn = 0; jn < 2; jn++) {
                uint32_t v0,v1,v2,v3;
                uint32_t bd = vb + (uint32_t)((ks*16 + wq + ((lane>>3)&1)*8)*144)
                            + (uint32_t)((wn*32 + jn*16)*2) + ((lane>>4)&1)*16;
                ldsm4t(v0,v1,v2,v3, bd);
                #pragma unroll
                for (int i = 0; i < 2; i++) {
                    mma4(acc[i][2*jn],   aa[i], v0, v1);
                    mma4(acc[i][2*jn+1], aa[i], v2, v3);
                }
            }
        }
        __syncthreads();
    }

    #pragma unroll
    for (int i = 0; i < 2; i++)
        #pragma unroll
        for (int hh2 = 0; hh2 < 2; hh2++) {
            lr[i][hh2] += __shfl_xor_sync(0xffffffffu, lr[i][hh2], 1);
            lr[i][hh2] += __shfl_xor_sync(0xffffffffu, lr[i][hh2], 2);
        }
    if (wn == 0 && tig == 0) {
        #pragma unroll
        for (int i = 0; i < 2; i++) {
            lsm[wm*32 + i*16 + gid]     = lr[i][0];
            lsm[wm*32 + i*16 + gid + 8] = lr[i][1];
        }
    }
    __syncthreads();
    {
        #pragma unroll
        for (int i = 0; i < 2; i++) {
            int r0 = wm*32 + i*16 + gid;
            float inv0 = 1.0f/lsm[r0], inv1 = 1.0f/lsm[r0+8];
            #pragma unroll
            for (int nf = 0; nf < 4; nf++) {
                int cb = wn*32 + nf*8 + 2*tig;
                OS[r0*68 + cb]       = acc[i][nf][0]*inv0;
                OS[r0*68 + cb + 1]   = acc[i][nf][1]*inv0;
                OS[(r0+8)*68 + cb]   = acc[i][nf][2]*inv1;
                OS[(r0+8)*68 + cb+1] = acc[i][nf][3]*inv1;
            }
        }
    }
    __syncthreads();
    {
        int r = tid>>1, c0 = (tid&1)*32;
        float inv = 1.0f/lsm[r];
        float x[32];
        const float* row = OS + r*68 + c0;
        #pragma unroll
        for (int g4 = 0; g4 < 8; g4++) *(float4*)(x+g4*4) = *(const float4*)(row+g4*4);
        size_t o = ((size_t)(b*S_+s0+r))*E_ + h*64 + c0;
        #pragma unroll
        for (int g8 = 0; g8 < 4; g8++)
            *(uint4*)(g_oa + o + g8*8) = pack8h(x + g8*8);
        size_t vi = ((size_t)(bh*S_+s0+r))*64 + c0;
        #pragma unroll
        for (int g8 = 0; g8 < 4; g8++) {
            uint4 wv = *(uint4*)(g_va + vi + g8*8);
            const __half* hp = (const __half*)&wv;
            float y[8];
            #pragma unroll
            for (int j = 0; j < 8; j++) y[j] = __half2float(hp[j]) * inv;
            *(uint4*)(g_v2 + vi + g8*8) = pack8h(y);
        }
    }
}

// ============ gemm_outv: out_v = P^T @ va2 (K=512) =========================
#define FV_AB 26112
#define FV_SZ 39936

__global__ void __launch_bounds__(256,2) gemm_outv()
{
    extern __shared__ char sm[];
    const uint32_t smb = cvta_s(sm);
    float* OS = (float*)sm;

    const int tid = threadIdx.x, w = tid>>5, lane = tid&31;
    const int wm = w&3, wn = w>>2;
    const int gid = lane>>2, tig = lane&3;
    const int bh = blockIdx.y, b = bh>>3, h = bh&7;
    const int t0 = blockIdx.x*128;

    const int cr = tid>>3, cc = tid&7;
    const __half* psrc = g_p  + (size_t)(bh*S_ + cr)*T_ + t0 + cc*8;
    const __half* asrc = g_v2 + (size_t)(bh*S_ + cr)*64 + cc*8;
    const uint32_t pdst = smb + (uint32_t)(cr*272 + cc*16);
    const uint32_t adst = smb + FV_AB + (uint32_t)(cr*144 + cc*16);

    #pragma unroll
    for (int c = 0; c < 2; c++) {
        CP16(pdst + c*8704,       psrc + (size_t)c*32*T_);
        CP16(pdst + c*8704 + 128, psrc + (size_t)c*32*T_ + 64);
        CP16(adst + c*4608,       asrc + (size_t)c*32*64);
        CPCOMMIT();
    }

    float acc[2][4][4] = {};

    for (int c = 0; c < 16; c++) {
        if (c < 15) { asm volatile("cp.async.wait_group 1;" ::: "memory"); }
        else        { asm volatile("cp.async.wait_group 0;" ::: "memory"); }
        __syncthreads();
        if (c + 2 < 16) {
            int j = (c+2)%3;
            CP16(pdst + j*8704,       psrc + (size_t)(c+2)*32*T_);
            CP16(pdst + j*8704 + 128, psrc + (size_t)(c+2)*32*T_ + 64);
            CP16(adst + j*4608,       asrc + (size_t)(c+2)*32*64);
            CPCOMMIT();
        }
        const uint32_t pb = smb + (uint32_t)((c%3)*8704);
        const uint32_t ab = smb + FV_AB + (uint32_t)((c%3)*4608);
        #pragma unroll
        for (int ks = 0; ks < 2; ks++) {
            uint32_t aa[2][4];
            #pragma unroll
            for (int i = 0; i < 2; i++) {
                uint32_t ad = pb + (uint32_t)(((ks*16 + (lane&7) + ((lane>>4)&1)*8)*136
                              + wm*32 + i*16 + ((lane>>3)&1)*8)*2);
                ldsm4t(aa[i][0], aa[i][1], aa[i][2], aa[i][3], ad);
            }
            #pragma unroll
            for (int jn = 0; jn < 2; jn++) {
                uint32_t v0,v1,v2,v3;
                uint32_t bd = ab + (uint32_t)(((ks*16 + (lane&7) + ((lane>>3)&1)*8)*72
                              + wn*32 + jn*16 + ((lane>>4)&1)*8)*2);
                ldsm4t(v0,v1,v2,v3, bd);
                #pragma unroll
                for (int i = 0; i < 2; i++) {
                    mma4(acc[i][2*jn],   aa[i], v0, v1);
                    mma4(acc[i][2*jn+1], aa[i], v2, v3);
                }
            }
        }
        __syncthreads();
    }
    {
        #pragma unroll
        for (int i = 0; i < 2; i++)
            #pragma unroll
            for (int nf = 0; nf < 4; nf++) {
                int rr = wm*32 + i*16 + gid, cbase = wn*32 + nf*8 + 2*tig;
                OS[rr*68 + cbase]       = acc[i][nf][0];
                OS[rr*68 + cbase + 1]   = acc[i][nf][1];
                OS[(rr+8)*68 + cbase]   = acc[i][nf][2];
                OS[(rr+8)*68 + cbase+1] = acc[i][nf][3];
            }
    }
    __syncthreads();
    {
        int r = tid>>1, c0 = (tid&1)*32;
        float x[32];
        const float* row = OS + r*68 + c0;
        #pragma unroll
        for (int g4 = 0; g4 < 8; g4++) *(float4*)(x+g4*4) = *(const float4*)(row+g4*4);
        size_t o = ((size_t)(b*T_+t0+r))*E_ + h*64 + c0;
        #pragma unroll
        for (int g8 = 0; g8 < 4; g8++)
            *(uint4*)(g_ov + o + g8*8) = pack8h(x + g8*8);
    }
}

// ============ raw-mma projection (128x128 tile, KC=32, 1-term fp16) ========
// smem: A plane 128x40 halves @0 (10240B); B plane 32x136 halves @10240 (8704B)
// epilogue reuses smem as fp32 OS 128x68 (34816B)
#define PJ_B   10240
#define PJ_SZ  34816

template<int AP, int OP>
__device__ __forceinline__ void proj_body(
    const float* A, const __half* Ap,
    const float* W, const float* bias, float* C, __half* Dh,
    int K, int N, int m0, int n0, float alpha, int lsh)
{
    extern __shared__ char sm[];
    const uint32_t smb = cvta_s(sm);
    const int tid = threadIdx.x, w = tid>>5, lane = tid&31;
    const int wm = w&3, wn = w>>2;
    const int gid = lane>>2, tig = lane&3, wq = lane&7;

    float acc[2][8][4] = {};
    const int nc = K >> 5;

    for (int c = 0; c < nc; c++) {
        const int k0 = c*32;
        __syncthreads();
        // A chunk 128x32 -> fp16 plane (stride 40 halves)
        if (AP == 0) {
            #pragma unroll
            for (int i = 0; i < 4; i++) {
                int q = tid + i*256, r = q>>3, c4 = (q&7)*4;
                float4 v = *(const float4*)(A + (size_t)(m0+r)*K + k0 + c4);
                *(uint2*)((__half*)sm + r*40 + c4) = pack4h(v.x, v.y, v.z, v.w);
            }
        } else {
            #pragma unroll
            for (int i = 0; i < 2; i++) {
                int cid = tid + i*256, r = cid>>2, cc = cid&3;
                const __half* src = Ap + (size_t)(m0+r)*K + k0;
                *(uint4*)((__half*)sm + r*40 + cc*8) = ((const uint4*)src)[cc];
            }
        }
        // B chunk 32x128 -> fp16 plane (stride 136 halves)
        #pragma unroll
        for (int i = 0; i < 4; i++) {
            int q = tid + i*256, k = q>>5, n4 = (q&31)*4;
            float4 v = *(const float4*)(W + (size_t)(k0+k)*N + n0 + n4);
            *(uint2*)((__half*)(sm + PJ_B) + k*136 + n4) = pack4h(v.x, v.y, v.z, v.w);
        }
        __syncthreads();
        #pragma unroll
        for (int ks = 0; ks < 2; ks++) {
            uint32_t ah[2][4];
            #pragma unroll
            for (int i = 0; i < 2; i++) {
                uint32_t ad = smb + (uint32_t)(((wm*32+i*16+(lane&15))*40
                             + ks*16 + (lane>>4)*8)*2);
                ldsm4(ah[i][0], ah[i][1], ah[i][2], ah[i][3], ad);
            }
            #pragma unroll
            for (int g = 0; g < 4; g++) {
                uint32_t bd = smb + PJ_B
                    + (uint32_t)((ks*16 + wq + ((lane>>3)&1)*8)*272)
                    + (uint32_t)((wn*64 + g*16)*2) + ((lane>>4)&1)*16;
                uint32_t b0,b1,b2,b3;
                ldsm4t(b0,b1,b2,b3, bd);
                #pragma unroll
                for (int i = 0; i < 2; i++) {
                    mma4(acc[i][2*g],   ah[i], b0, b1);
                    mma4(acc[i][2*g+1], ah[i], b2, b3);
                }
            }
        }
    }

    float* OS = (float*)sm;
    #pragma unroll
    for (int hf = 0; hf < 2; hf++) {
        __syncthreads();
        if (wn == hf) {
            #pragma unroll
            for (int i = 0; i < 2; i++)
                #pragma unroll
                for (int nf = 0; nf < 8; nf++) {
                    int r0 = wm*32 + i*16 + gid, cb = nf*8 + 2*tig;
                    OS[r0*68 + cb]       = acc[i][nf][0];
                    OS[r0*68 + cb + 1]   = acc[i][nf][1];
                    OS[(r0+8)*68 + cb]   = acc[i][nf][2];
                    OS[(r0+8)*68 + cb+1] = acc[i][nf][3];
                }
        }
        __syncthreads();
        const int r = tid>>1, c0 = (tid&1)*32;
        const int nbase = n0 + hf*64;
        if (OP == 0) {
            const int Lm1 = (1 << lsh) - 1;
            int m = m0 + r, bb = m >> lsh, tok = m & Lm1;
            int hh = nbase >> 6;
            size_t o = (((size_t)(bb*H_ + hh) << lsh) + tok) * 64 + c0;
            #pragma unroll
            for (int g8 = 0; g8 < 4; g8++) {
                float x[8];
                #pragma unroll
                for (int j = 0; j < 8; j++)
                    x[j] = alpha * (OS[r*68 + c0 + g8*8 + j]
                                    + __ldg(bias + nbase + c0 + g8*8 + j));
                *(uint4*)(Dh + o + g8*8) = pack8h(x);
            }
        } else {
            float* crow = C + (size_t)(m0+r)*N + nbase + c0;
            #pragma unroll
            for (int g4 = 0; g4 < 8; g4++) {
                float4 v;
                v.x = OS[r*68 + c0 + g4*4 + 0] + __ldg(bias + nbase + c0 + g4*4 + 0);
                v.y = OS[r*68 + c0 + g4*4 + 1] + __ldg(bias + nbase + c0 + g4*4 + 1);
                v.z = OS[r*68 + c0 + g4*4 + 2] + __ldg(bias + nbase + c0 + g4*4 + 2);
                v.w = OS[r*68 + c0 + g4*4 + 3] + __ldg(bias + nbase + c0 + g4*4 + 3);
                *(float4*)(crow + g4*4) = v;
            }
        }
    }
}

__global__ void __launch_bounds__(256,2) proj_in2(
    const float* A, const float* W1, const float* b1, float a1, __half* D1,
    const float* W2, const float* b2, float a2, __half* D2, int K, int lsh)
{
    const int sel = blockIdx.x >> 2;
    proj_body<0,0>(A, 0,
                   sel ? W2 : W1, sel ? b2 : b1, 0, sel ? D2 : D1,
                   K, 512, blockIdx.y*128, (blockIdx.x & 3)*128,
                   sel ? a2 : a1, lsh);
}

__global__ void __launch_bounds__(256,2) proj_out2(
    const float* W1, const float* b1, float* C1,
    const float* W2, const float* b2, float* C2)
{
    const bool r2 = blockIdx.y >= 128;
    if (r2 && blockIdx.x >= 2) return;
    proj_body<1,1>(0, r2 ? g_oa : g_ov,
                   r2 ? W2 : W1, r2 ? b2 : b1, r2 ? C2 : C1, 0,
                   512, r2 ? 256 : 512,
                   (r2 ? blockIdx.y - 128 : blockIdx.y)*128, blockIdx.x*128,
                   1.0f, 0);
}

// ---------------------------------------------------------------------------
extern "C" void kernel_launch(void* const* d_in, const int* in_sizes, int n_in,
                              void* d_out, int out_size)
{
    const float* v    = (const float*)d_in[0];
    const float* a    = (const float*)d_in[1];
    const float* w_vq = (const float*)d_in[2];
    const float* b_vq = (const float*)d_in[3];
    const float* w_ak = (const float*)d_in[4];
    const float* b_ak = (const float*)d_in[5];
    const float* w_vv = (const float*)d_in[6];
    const float* b_vv = (const float*)d_in[7];
    const float* w_av = (const float*)d_in[8];
    const float* b_av = (const float*)d_in[9];
    const float* w_ov = (const float*)d_in[10];
    const float* b_ov = (const float*)d_in[11];
    const float* w_oa = (const float*)d_in[12];
    const float* b_oa = (const float*)d_in[13];
    float* out = (float*)d_out;

    __half *q, *k, *vv, *va;
    cudaGetSymbolAddress((void**)&q,  g_q);  cudaGetSymbolAddress((void**)&k,  g_k);
    cudaGetSymbolAddress((void**)&vv, g_vv); cudaGetSymbolAddress((void**)&va, g_va);

    cudaFuncSetAttribute(proj_in2,  cudaFuncAttributeMaxDynamicSharedMemorySize, PJ_SZ);
    cudaFuncSetAttribute(proj_out2, cudaFuncAttributeMaxDynamicSharedMemorySize, PJ_SZ);
    cudaFuncSetAttribute(scores_strip, cudaFuncAttributeMaxDynamicSharedMemorySize, SS_SZ);
    cudaFuncSetAttribute(gemm_outa, cudaFuncAttributeMaxDynamicSharedMemorySize, OA_SZ);
    cudaFuncSetAttribute(gemm_outv, cudaFuncAttributeMaxDynamicSharedMemorySize, FV_SZ);

    const float ALQ = 0.125f * 1.4426950408889634f;   // fold log2(e)
    proj_in2<<<dim3(8,128), 256, PJ_SZ>>>(v, w_vq, b_vq, ALQ, q,
                                          w_vv, b_vv, 1.0f, vv, VD_, 11);
    proj_in2<<<dim3(8,32), 256, PJ_SZ>>>(a, w_ak, b_ak, 1.0f, k,
                                         w_av, b_av, 1.0f, va, AD_, 9);

    scores_strip<<<dim3(4, BH_), 256, SS_SZ>>>();
    gemm_outa<<<dim3(S_/128, BH_), 256, OA_SZ>>>();
    gemm_outv<<<dim3(T_/128, BH_), 256, FV_SZ>>>();

    proj_out2<<<dim3(4,160), 256, PJ_SZ>>>(w_ov, b_ov, out,
                                           w_oa, b_oa, out + (size_t)B_*T_*VD_);
}

// round 15
// speedup vs baseline: 1.9033x; 1.1703x over previous
#include <cuda_runtime.h>
#include <cuda_fp16.h>
#include <cstdint>

#define B_ 8
#define T_ 2048
#define S_ 512
#define VD_ 512
#define AD_ 256
#define E_ 512
#define H_ 8
#define BH_ 64

__device__ __half g_q [(size_t)BH_*T_*64];
__device__ __half g_k [(size_t)BH_*S_*64];
__device__ __half g_vv[(size_t)BH_*T_*64];
__device__ __half g_va[(size_t)BH_*S_*64];
__device__ __half g_v2[(size_t)BH_*S_*64];          // va / l
__device__ __half g_p [(size_t)BH_*S_*T_];          // exp2(S) fp16
__device__ __half g_ov[(size_t)B_*T_*E_];
__device__ __half g_oa[(size_t)B_*S_*E_];
// fp16 copies of inputs/weights (converted once)
__device__ __half g_vh [(size_t)B_*T_*VD_];
__device__ __half g_ah [(size_t)B_*S_*AD_];
__device__ __half g_wvq[VD_*E_], g_wak[AD_*E_], g_wvv[VD_*E_], g_wav[AD_*E_];
__device__ __half g_wov[E_*VD_], g_woa[E_*AD_];

__device__ __forceinline__ float ex2f(float x) {
    float r; asm("ex2.approx.f32 %0, %1;" : "=f"(r) : "f"(x)); return r;
}
__device__ __forceinline__ uint32_t cvta_s(const void* p) {
    uint32_t r;
    asm("{ .reg .u64 t; cvta.to.shared.u64 t, %1; cvt.u32.u64 %0, t; }" : "=r"(r) : "l"(p));
    return r;
}
__device__ __forceinline__ uint32_t h2u(float x, float y) {
    __half2 h = __floats2half2_rn(x, y); return *(uint32_t*)&h;
}
__device__ __forceinline__ uint4 pack8h(const float* x) {
    union { __half b[8]; uint4 u; } U;
    #pragma unroll
    for (int j = 0; j < 8; j++) U.b[j] = __float2half_rn(x[j]);
    return U.u;
}
__device__ __forceinline__ void ldsm4(uint32_t& r0, uint32_t& r1, uint32_t& r2, uint32_t& r3,
                                      uint32_t a) {
    asm volatile("ldmatrix.sync.aligned.m8n8.x4.shared.b16 {%0,%1,%2,%3}, [%4];"
                 : "=r"(r0), "=r"(r1), "=r"(r2), "=r"(r3) : "r"(a));
}
__device__ __forceinline__ void ldsm4t(uint32_t& r0, uint32_t& r1, uint32_t& r2, uint32_t& r3,
                                       uint32_t a) {
    asm volatile("ldmatrix.sync.aligned.m8n8.x4.trans.shared.b16 {%0,%1,%2,%3}, [%4];"
                 : "=r"(r0), "=r"(r1), "=r"(r2), "=r"(r3) : "r"(a));
}
__device__ __forceinline__ void mma4(float* c, const uint32_t* a, uint32_t b0, uint32_t b1) {
    asm volatile("mma.sync.aligned.m16n8k16.row.col.f32.f16.f16.f32 "
                 "{%0,%1,%2,%3}, {%4,%5,%6,%7}, {%8,%9}, {%0,%1,%2,%3};"
                 : "+f"(c[0]), "+f"(c[1]), "+f"(c[2]), "+f"(c[3])
                 : "r"(a[0]), "r"(a[1]), "r"(a[2]), "r"(a[3]), "r"(b0), "r"(b1));
}
#define CP16(dst, src) \
    asm volatile("cp.async.cg.shared.global [%0], [%1], 16;" :: "r"(dst), "l"(src))
#define CPCOMMIT() asm volatile("cp.async.commit_group;" ::: "memory")

// ============ f2h: fp32 -> fp16, 8 elems/thread =============================
__global__ void __launch_bounds__(256) f2h(const float* __restrict__ s,
                                           __half* __restrict__ d)
{
    size_t i = ((size_t)blockIdx.x*256 + threadIdx.x)*8;
    float x[8];
    *(float4*)x     = *(const float4*)(s+i);
    *(float4*)(x+4) = *(const float4*)(s+i+4);
    *(uint4*)(d+i) = pack8h(x);
}

// ============ scores_strip: P[s0:+128][all t] = exp2(K @ Q^T) ==============
#define SS_Q  36864
#define SS_SZ 92160

__global__ void __launch_bounds__(256,2) scores_strip()
{
    extern __shared__ char sm[];
    const uint32_t smb = cvta_s(sm);
    __half* PS = (__half*)sm;

    const int tid = threadIdx.x, w = tid>>5, lane = tid&31;
    const int gid = lane>>2, tig = lane&3, wq = lane&7;
    const int wm = w&3, wn = w>>2;
    const int bh = blockIdx.y;
    const int s0 = blockIdx.x*128;

    {
        const uint4* ks = (const uint4*)(g_k + ((size_t)bh*S_+s0)*64);
        #pragma unroll
        for (int i = 0; i < 4; i++) {
            int q = tid + i*256, r = q>>3, c = q&7;
            *(uint4*)((__half*)sm + r*72 + c*8) = ks[q];
        }
    }
    __syncthreads();
    uint32_t KA[4][2][4];
    #pragma unroll
    for (int ksi = 0; ksi < 4; ksi++)
        #pragma unroll
        for (int i = 0; i < 2; i++) {
            uint32_t ad = smb + (uint32_t)(((wm*32+i*16+(lane&15))*72 + (lane>>4)*8)*2)
                        + ksi*32;
            ldsm4(KA[ksi][i][0], KA[ksi][i][1], KA[ksi][i][2], KA[ksi][i][3], ad);
        }
    __syncthreads();

    auto issueQ = [&](int it, int j) {
        const __half* qs = g_q + ((size_t)bh*T_ + it*128)*64;
        uint32_t base = smb + SS_Q + (uint32_t)(j*18432);
        #pragma unroll
        for (int i = 0; i < 4; i++) {
            int q = tid + i*256, r = q>>3, c = q&7;
            CP16(base + (uint32_t)(r*144 + c*16), qs + (size_t)r*64 + c*8);
        }
        CPCOMMIT();
    };
    issueQ(0, 0); issueQ(1, 1);

    const uint32_t qlo = (uint32_t)((wq + ((lane>>4)&1)*8)*144) + ((lane>>3)&1)*16;

    for (int it = 0; it < 16; it++) {
        if (it < 15) { asm volatile("cp.async.wait_group 1;" ::: "memory"); }
        else         { asm volatile("cp.async.wait_group 0;" ::: "memory"); }
        __syncthreads();
        if (it + 2 < 16) issueQ(it+2, (it+2)%3);

        const uint32_t qb = smb + SS_Q + (uint32_t)((it%3)*18432);
        float acc[2][8][4] = {};
        #pragma unroll
        for (int ksi = 0; ksi < 4; ksi++) {
            #pragma unroll
            for (int jb = 0; jb < 4; jb++) {
                uint32_t q0,q1,q2,q3;
                ldsm4(q0,q1,q2,q3, qb + qlo + (wn*64 + jb*16)*144 + ksi*32);
                #pragma unroll
                for (int i = 0; i < 2; i++) {
                    mma4(acc[i][jb*2],   KA[ksi][i], q0, q1);
                    mma4(acc[i][jb*2+1], KA[ksi][i], q2, q3);
                }
            }
        }
        #pragma unroll
        for (int i = 0; i < 2; i++)
            #pragma unroll
            for (int nf = 0; nf < 8; nf++) {
                int col = wn*64 + nf*8 + 2*tig;
                int r0 = wm*32 + i*16 + gid;
                *(uint32_t*)(PS + r0*136 + col) =
                    h2u(ex2f(acc[i][nf][0]), ex2f(acc[i][nf][1]));
                *(uint32_t*)(PS + (r0+8)*136 + col) =
                    h2u(ex2f(acc[i][nf][2]), ex2f(acc[i][nf][3]));
            }
        __syncthreads();
        {
            int r = tid>>1, c0 = (tid&1)*64;
            const __half* ps = PS + r*136 + c0;
            __half* gp = g_p + ((size_t)(bh*S_+s0+r))*T_ + it*128 + c0;
            #pragma unroll
            for (int i = 0; i < 8; i++)
                *(uint4*)(gp + i*8) = *(const uint4*)(ps + i*8);
        }
        __syncthreads();
    }
}

// ============ gemm_outa: out_a = (P @ vv)/l ; va2 = va/l ===================
#define OA_VB 30720
#define OA_LS 45056
#define OA_SZ 45568

__global__ void __launch_bounds__(256,2) gemm_outa()
{
    extern __shared__ char sm[];
    const uint32_t smb = cvta_s(sm);
    float* lsm = (float*)(sm + OA_LS);
    float* OS  = (float*)sm;

    const int tid = threadIdx.x, w = tid>>5, lane = tid&31;
    const int wm = w&3, wn = w>>2;
    const int gid = lane>>2, tig = lane&3, wq = lane&7;
    const int bh = blockIdx.y, b = bh>>3, h = bh&7;
    const int s0 = blockIdx.x*128;

    const int pr = tid>>1, pc = (tid&1)*16;
    const __half* psrc = g_p + (size_t)(bh*S_ + s0 + pr)*T_ + pc;
    const uint32_t pdst = smb + (uint32_t)(pr*80 + pc*2);
    const int vr = tid>>3, vc = tid&7;
    const __half* vsrc = g_vv + (size_t)bh*T_*64 + (size_t)vr*64 + vc*8;
    const uint32_t vdst = smb + OA_VB + (uint32_t)(vr*144 + vc*16);

    #pragma unroll
    for (int c = 0; c < 2; c++) {
        CP16(pdst + c*10240,      psrc + (size_t)c*32);
        CP16(pdst + c*10240 + 16, psrc + (size_t)c*32 + 8);
        CP16(vdst + c*4608,       vsrc + (size_t)c*32*64);
        CPCOMMIT();
    }

    float acc[2][4][4] = {};
    float lr[2][2] = {};

    for (int c = 0; c < 64; c++) {
        if (c < 63) { asm volatile("cp.async.wait_group 1;" ::: "memory"); }
        else        { asm volatile("cp.async.wait_group 0;" ::: "memory"); }
        __syncthreads();
        if (c + 2 < 64) {
            int j = (c+2)%3;
            CP16(pdst + j*10240,      psrc + (size_t)(c+2)*32);
            CP16(pdst + j*10240 + 16, psrc + (size_t)(c+2)*32 + 8);
            CP16(vdst + j*4608,       vsrc + (size_t)(c+2)*32*64);
            CPCOMMIT();
        }
        const uint32_t pb = smb + (uint32_t)((c%3)*10240);
        const uint32_t vb = smb + OA_VB + (uint32_t)((c%3)*4608);
        #pragma unroll
        for (int ks = 0; ks < 2; ks++) {
            uint32_t aa[2][4];
            #pragma unroll
            for (int i = 0; i < 2; i++) {
                uint32_t ad = pb + (uint32_t)(((wm*32+i*16+(lane&15))*40
                             + ks*16 + (lane>>4)*8)*2);
                ldsm4(aa[i][0], aa[i][1], aa[i][2], aa[i][3], ad);
                if (wn == 0) {
                    float2 f0 = __half22float2(*(__half2*)&aa[i][0]);
                    float2 f2 = __half22float2(*(__half2*)&aa[i][2]);
                    float2 f1 = __half22float2(*(__half2*)&aa[i][1]);
                    float2 f3 = __half22float2(*(__half2*)&aa[i][3]);
                    lr[i][0] += f0.x+f0.y+f2.x+f2.y;
                    lr[i][1] += f1.x+f1.y+f3.x+f3.y;
                }
            }
            #pragma unroll
            for (int jn = 0; jn < 2; jn++) {
                uint32_t v0,v1,v2,v3;
                uint32_t bd = vb + (uint32_t)((ks*16 + wq + ((lane>>3)&1)*8)*144)
                            + (uint32_t)((wn*32 + jn*16)*2) + ((lane>>4)&1)*16;
                ldsm4t(v0,v1,v2,v3, bd);
                #pragma unroll
                for (int i = 0; i < 2; i++) {
                    mma4(acc[i][2*jn],   aa[i], v0, v1);
                    mma4(acc[i][2*jn+1], aa[i], v2, v3);
                }
            }
        }
        __syncthreads();
    }

    #pragma unroll
    for (int i = 0; i < 2; i++)
        #pragma unroll
        for (int hh2 = 0; hh2 < 2; hh2++) {
            lr[i][hh2] += __shfl_xor_sync(0xffffffffu, lr[i][hh2], 1);
            lr[i][hh2] += __shfl_xor_sync(0xffffffffu, lr[i][hh2], 2);
        }
    if (wn == 0 && tig == 0) {
        #pragma unroll
        for (int i = 0; i < 2; i++) {
            lsm[wm*32 + i*16 + gid]     = lr[i][0];
            lsm[wm*32 + i*16 + gid + 8] = lr[i][1];
        }
    }
    __syncthreads();
    {
        #pragma unroll
        for (int i = 0; i < 2; i++) {
            int r0 = wm*32 + i*16 + gid;
            float inv0 = 1.0f/lsm[r0], inv1 = 1.0f/lsm[r0+8];
            #pragma unroll
            for (int nf = 0; nf < 4; nf++) {
                int cb = wn*32 + nf*8 + 2*tig;
                OS[r0*68 + cb]       = acc[i][nf][0]*inv0;
                OS[r0*68 + cb + 1]   = acc[i][nf][1]*inv0;
                OS[(r0+8)*68 + cb]   = acc[i][nf][2]*inv1;
                OS[(r0+8)*68 + cb+1] = acc[i][nf][3]*inv1;
            }
        }
    }
    __syncthreads();
    {
        int r = tid>>1, c0 = (tid&1)*32;
        float inv = 1.0f/lsm[r];
        float x[32];
        const float* row = OS + r*68 + c0;
        #pragma unroll
        for (int g4 = 0; g4 < 8; g4++) *(float4*)(x+g4*4) = *(const float4*)(row+g4*4);
        size_t o = ((size_t)(b*S_+s0+r))*E_ + h*64 + c0;
        #pragma unroll
        for (int g8 = 0; g8 < 4; g8++)
            *(uint4*)(g_oa + o + g8*8) = pack8h(x + g8*8);
        size_t vi = ((size_t)(bh*S_+s0+r))*64 + c0;
        #pragma unroll
        for (int g8 = 0; g8 < 4; g8++) {
            uint4 wv = *(uint4*)(g_va + vi + g8*8);
            const __half* hp = (const __half*)&wv;
            float y[8];
            #pragma unroll
            for (int j = 0; j < 8; j++) y[j] = __half2float(hp[j]) * inv;
            *(uint4*)(g_v2 + vi + g8*8) = pack8h(y);
        }
    }
}

// ============ gemm_outv: out_v = P^T @ va2 (K=512) =========================
#define FV_AB 26112
#define FV_SZ 39936

__global__ void __launch_bounds__(256,2) gemm_outv()
{
    extern __shared__ char sm[];
    const uint32_t smb = cvta_s(sm);
    float* OS = (float*)sm;

    const int tid = threadIdx.x, w = tid>>5, lane = tid&31;
    const int wm = w&3, wn = w>>2;
    const int gid = lane>>2, tig = lane&3;
    const int bh = blockIdx.y, b = bh>>3, h = bh&7;
    const int t0 = blockIdx.x*128;

    const int cr = tid>>3, cc = tid&7;
    const __half* psrc = g_p  + (size_t)(bh*S_ + cr)*T_ + t0 + cc*8;
    const __half* asrc = g_v2 + (size_t)(bh*S_ + cr)*64 + cc*8;
    const uint32_t pdst = smb + (uint32_t)(cr*272 + cc*16);
    const uint32_t adst = smb + FV_AB + (uint32_t)(cr*144 + cc*16);

    #pragma unroll
    for (int c = 0; c < 2; c++) {
        CP16(pdst + c*8704,       psrc + (size_t)c*32*T_);
        CP16(pdst + c*8704 + 128, psrc + (size_t)c*32*T_ + 64);
        CP16(adst + c*4608,       asrc + (size_t)c*32*64);
        CPCOMMIT();
    }

    float acc[2][4][4] = {};

    for (int c = 0; c < 16; c++) {
        if (c < 15) { asm volatile("cp.async.wait_group 1;" ::: "memory"); }
        else        { asm volatile("cp.async.wait_group 0;" ::: "memory"); }
        __syncthreads();
        if (c + 2 < 16) {
            int j = (c+2)%3;
            CP16(pdst + j*8704,       psrc + (size_t)(c+2)*32*T_);
            CP16(pdst + j*8704 + 128, psrc + (size_t)(c+2)*32*T_ + 64);
            CP16(adst + j*4608,       asrc + (size_t)(c+2)*32*64);
            CPCOMMIT();
        }
        const uint32_t pb = smb + (uint32_t)((c%3)*8704);
        const uint32_t ab = smb + FV_AB + (uint32_t)((c%3)*4608);
        #pragma unroll
        for (int ks = 0; ks < 2; ks++) {
            uint32_t aa[2][4];
            #pragma unroll
            for (int i = 0; i < 2; i++) {
                uint32_t ad = pb + (uint32_t)(((ks*16 + (lane&7) + ((lane>>4)&1)*8)*136
                              + wm*32 + i*16 + ((lane>>3)&1)*8)*2);
                ldsm4t(aa[i][0], aa[i][1], aa[i][2], aa[i][3], ad);
            }
            #pragma unroll
            for (int jn = 0; jn < 2; jn++) {
                uint32_t v0,v1,v2,v3;
                uint32_t bd = ab + (uint32_t)(((ks*16 + (lane&7) + ((lane>>3)&1)*8)*72
                              + wn*32 + jn*16 + ((lane>>4)&1)*8)*2);
                ldsm4t(v0,v1,v2,v3, bd);
                #pragma unroll
                for (int i = 0; i < 2; i++) {
                    mma4(acc[i][2*jn],   aa[i], v0, v1);
                    mma4(acc[i][2*jn+1], aa[i], v2, v3);
                }
            }
        }
        __syncthreads();
    }
    {
        #pragma unroll
        for (int i = 0; i < 2; i++)
            #pragma unroll
            for (int nf = 0; nf < 4; nf++) {
                int rr = wm*32 + i*16 + gid, cbase = wn*32 + nf*8 + 2*tig;
                OS[rr*68 + cbase]       = acc[i][nf][0];
                OS[rr*68 + cbase + 1]   = acc[i][nf][1];
                OS[(rr+8)*68 + cbase]   = acc[i][nf][2];
                OS[(rr+8)*68 + cbase+1] = acc[i][nf][3];
            }
    }
    __syncthreads();
    {
        int r = tid>>1, c0 = (tid&1)*32;
        float x[32];
        const float* row = OS + r*68 + c0;
        #pragma unroll
        for (int g4 = 0; g4 < 8; g4++) *(float4*)(x+g4*4) = *(const float4*)(row+g4*4);
        size_t o = ((size_t)(b*T_+t0+r))*E_ + h*64 + c0;
        #pragma unroll
        for (int g8 = 0; g8 < 4; g8++)
            *(uint4*)(g_ov + o + g8*8) = pack8h(x + g8*8);
    }
}

// ============ pipelined fp16 projection (128x128 tile, KC=32) ==============
// 3-buffer cp.async ring: buf = A 128x40 halves (10240 B) + W 32x136 (8704 B)
#define PJ_BUF 18944
#define PJ_SZ  56832

template<int OP>
__device__ __forceinline__ void proj_body(
    const __half* Ap, const __half* Wp, const float* bias, float* C, __half* Dh,
    int K, int N, int m0, int n0, float alpha, int lsh)
{
    extern __shared__ char sm[];
    const uint32_t smb = cvta_s(sm);
    const int tid = threadIdx.x, w = tid>>5, lane = tid&31;
    const int wm = w&3, wn = w>>2;
    const int gid = lane>>2, tig = lane&3, wq = lane&7;

    float acc[2][8][4] = {};
    const int nc = K >> 5;

    auto issue = [&](int c, int j) {
        const int k0 = c*32;
        uint32_t base = smb + (uint32_t)(j*PJ_BUF);
        #pragma unroll
        for (int i = 0; i < 2; i++) {
            int idx = tid + i*256, r = idx>>2, c4 = idx&3;
            CP16(base + (uint32_t)(r*80 + c4*16),
                 Ap + (size_t)(m0+r)*K + k0 + c4*8);
        }
        #pragma unroll
        for (int i = 0; i < 2; i++) {
            int idx = tid + i*256, k = idx>>4, n8 = idx&15;
            CP16(base + 10240 + (uint32_t)(k*272 + n8*16),
                 Wp + (size_t)(k0+k)*N + n0 + n8*8);
        }
        CPCOMMIT();
    };
    issue(0, 0); issue(1, 1);

    for (int c = 0; c < nc; c++) {
        if (c < nc-1) { asm volatile("cp.async.wait_group 1;" ::: "memory"); }
        else          { asm volatile("cp.async.wait_group 0;" ::: "memory"); }
        __syncthreads();
        if (c + 2 < nc) issue(c+2, (c+2)%3);
        const uint32_t pb = smb + (uint32_t)((c%3)*PJ_BUF);
        #pragma unroll
        for (int ks = 0; ks < 2; ks++) {
            uint32_t ah[2][4];
            #pragma unroll
            for (int i = 0; i < 2; i++) {
                uint32_t ad = pb + (uint32_t)(((wm*32+i*16+(lane&15))*40
                             + ks*16 + (lane>>4)*8)*2);
                ldsm4(ah[i][0], ah[i][1], ah[i][2], ah[i][3], ad);
            }
            #pragma unroll
            for (int g = 0; g < 4; g++) {
                uint32_t bd = pb + 10240
                    + (uint32_t)((ks*16 + wq + ((lane>>3)&1)*8)*272)
                    + (uint32_t)((wn*64 + g*16)*2) + ((lane>>4)&1)*16;
                uint32_t b0,b1,b2,b3;
                ldsm4t(b0,b1,b2,b3, bd);
                #pragma unroll
                for (int i = 0; i < 2; i++) {
                    mma4(acc[i][2*g],   ah[i], b0, b1);
                    mma4(acc[i][2*g+1], ah[i], b2, b3);
                }
            }
        }
        __syncthreads();
    }

    float* OS = (float*)sm;
    #pragma unroll
    for (int hf = 0; hf < 2; hf++) {
        __syncthreads();
        if (wn == hf) {
            #pragma unroll
            for (int i = 0; i < 2; i++)
                #pragma unroll
                for (int nf = 0; nf < 8; nf++) {
                    int r0 = wm*32 + i*16 + gid, cb = nf*8 + 2*tig;
                    OS[r0*68 + cb]       = acc[i][nf][0];
                    OS[r0*68 + cb + 1]   = acc[i][nf][1];
                    OS[(r0+8)*68 + cb]   = acc[i][nf][2];
                    OS[(r0+8)*68 + cb+1] = acc[i][nf][3];
                }
        }
        __syncthreads();
        const int r = tid>>1, c0 = (tid&1)*32;
        const int nbase = n0 + hf*64;
        if (OP == 0) {
            const int Lm1 = (1 << lsh) - 1;
            int m = m0 + r, bb = m >> lsh, tok = m & Lm1;
            int hh = nbase >> 6;
            size_t o = (((size_t)(bb*H_ + hh) << lsh) + tok) * 64 + c0;
            #pragma unroll
            for (int g8 = 0; g8 < 4; g8++) {
                float x[8];
                #pragma unroll
                for (int j = 0; j < 8; j++)
                    x[j] = alpha * (OS[r*68 + c0 + g8*8 + j]
                                    + __ldg(bias + nbase + c0 + g8*8 + j));
                *(uint4*)(Dh + o + g8*8) = pack8h(x);
            }
        } else {
            float* crow = C + (size_t)(m0+r)*N + nbase + c0;
            #pragma unroll
            for (int g4 = 0; g4 < 8; g4++) {
                float4 v;
                v.x = OS[r*68 + c0 + g4*4 + 0] + __ldg(bias + nbase + c0 + g4*4 + 0);
                v.y = OS[r*68 + c0 + g4*4 + 1] + __ldg(bias + nbase + c0 + g4*4 + 1);
                v.z = OS[r*68 + c0 + g4*4 + 2] + __ldg(bias + nbase + c0 + g4*4 + 2);
                v.w = OS[r*68 + c0 + g4*4 + 3] + __ldg(bias + nbase + c0 + g4*4 + 3);
                *(float4*)(crow + g4*4) = v;
            }
        }
    }
}

__global__ void __launch_bounds__(256,2) proj_in2(
    const __half* A, const __half* W1, const float* b1, float a1, __half* D1,
    const __half* W2, const float* b2, float a2, __half* D2, int K, int lsh)
{
    const int sel = blockIdx.x >> 2;
    proj_body<0>(A, sel ? W2 : W1, sel ? b2 : b1, 0, sel ? D2 : D1,
                 K, 512, blockIdx.y*128, (blockIdx.x & 3)*128,
                 sel ? a2 : a1, lsh);
}

__global__ void __launch_bounds__(256,2) proj_out2(
    const float* b1, float* C1, const float* b2, float* C2)
{
    const bool r2 = blockIdx.y >= 128;
    if (r2 && blockIdx.x >= 2) return;
    proj_body<1>(r2 ? g_oa : g_ov, r2 ? g_woa : g_wov,
                 r2 ? b2 : b1, r2 ? C2 : C1, 0,
                 512, r2 ? 256 : 512,
                 (r2 ? blockIdx.y - 128 : blockIdx.y)*128, blockIdx.x*128,
                 1.0f, 0);
}

// ---------------------------------------------------------------------------
extern "C" void kernel_launch(void* const* d_in, const int* in_sizes, int n_in,
                              void* d_out, int out_size)
{
    const float* v    = (const float*)d_in[0];
    const float* a    = (const float*)d_in[1];
    const float* w_vq = (const float*)d_in[2];
    const float* b_vq = (const float*)d_in[3];
    const float* w_ak = (const float*)d_in[4];
    const float* b_ak = (const float*)d_in[5];
    const float* w_vv = (const float*)d_in[6];
    const float* b_vv = (const float*)d_in[7];
    const float* w_av = (const float*)d_in[8];
    const float* b_av = (const float*)d_in[9];
    const float* w_ov = (const float*)d_in[10];
    const float* b_ov = (const float*)d_in[11];
    const float* w_oa = (const float*)d_in[12];
    const float* b_oa = (const float*)d_in[13];
    float* out = (float*)d_out;

    __half *q, *k, *vv, *va, *vh, *ah, *wvq, *wak, *wvv, *wav, *wov, *woa;
    cudaGetSymbolAddress((void**)&q,   g_q);   cudaGetSymbolAddress((void**)&k,   g_k);
    cudaGetSymbolAddress((void**)&vv,  g_vv);  cudaGetSymbolAddress((void**)&va,  g_va);
    cudaGetSymbolAddress((void**)&vh,  g_vh);  cudaGetSymbolAddress((void**)&ah,  g_ah);
    cudaGetSymbolAddress((void**)&wvq, g_wvq); cudaGetSymbolAddress((void**)&wak, g_wak);
    cudaGetSymbolAddress((void**)&wvv, g_wvv); cudaGetSymbolAddress((void**)&wav, g_wav);
    cudaGetSymbolAddress((void**)&wov, g_wov); cudaGetSymbolAddress((void**)&woa, g_woa);

    cudaFuncSetAttribute(proj_in2,  cudaFuncAttributeMaxDynamicSharedMemorySize, PJ_SZ);
    cudaFuncSetAttribute(proj_out2, cudaFuncAttributeMaxDynamicSharedMemorySize, PJ_SZ);
    cudaFuncSetAttribute(scores_strip, cudaFuncAttributeMaxDynamicSharedMemorySize, SS_SZ);
    cudaFuncSetAttribute(gemm_outa, cudaFuncAttributeMaxDynamicSharedMemorySize, OA_SZ);
    cudaFuncSetAttribute(gemm_outv, cudaFuncAttributeMaxDynamicSharedMemorySize, FV_SZ);

    // fp32 -> fp16 conversions (same rounding points as before)
    f2h<<<(B_*T_*VD_)/2048, 256>>>(v, vh);
    f2h<<<(B_*S_*AD_)/2048, 256>>>(a, ah);
    f2h<<<(VD_*E_)/2048, 256>>>(w_vq, wvq);
    f2h<<<(AD_*E_)/2048, 256>>>(w_ak, wak);
    f2h<<<(VD_*E_)/2048, 256>>>(w_vv, wvv);
    f2h<<<(AD_*E_)/2048, 256>>>(w_av, wav);
    f2h<<<(E_*VD_)/2048, 256>>>(w_ov, wov);
    f2h<<<(E_*AD_)/2048, 256>>>(w_oa, woa);

    const float ALQ = 0.125f * 1.4426950408889634f;   // fold log2(e)
    proj_in2<<<dim3(8,128), 256, PJ_SZ>>>(vh, wvq, b_vq, ALQ, q,
                                          wvv, b_vv, 1.0f, vv, VD_, 11);
    proj_in2<<<dim3(8,32), 256, PJ_SZ>>>(ah, wak, b_ak, 1.0f, k,
                                         wav, b_av, 1.0f, va, AD_, 9);

    scores_strip<<<dim3(4, BH_), 256, SS_SZ>>>();
    gemm_outa<<<dim3(S_/128, BH_), 256, OA_SZ>>>();
    gemm_outv<<<dim3(T_/128, BH_), 256, FV_SZ>>>();

    proj_out2<<<dim3(4,160), 256, PJ_SZ>>>(b_ov, out,
                                           b_oa, out + (size_t)B_*T_*VD_);
}

// round 16
// speedup vs baseline: 2.0698x; 1.0875x over previous
#include <cuda_runtime.h>
#include <cuda_fp16.h>
#include <cstdint>

#define B_ 8
#define T_ 2048
#define S_ 512
#define VD_ 512
#define AD_ 256
#define E_ 512
#define H_ 8
#define BH_ 64

__device__ __half g_q [(size_t)BH_*T_*64];
__device__ __half g_k [(size_t)BH_*S_*64];
__device__ __half g_vv[(size_t)BH_*T_*64];
__device__ __half g_va[(size_t)BH_*S_*64];
__device__ __half g_v2[(size_t)BH_*S_*64];          // va / l
__device__ __half g_p [(size_t)BH_*S_*T_];          // exp2(S) fp16
__device__ __half g_ov[(size_t)B_*T_*E_];
__device__ __half g_oa[(size_t)B_*S_*E_];
__device__ __half g_vh [(size_t)B_*T_*VD_];
__device__ __half g_ah [(size_t)B_*S_*AD_];
__device__ __half g_wvq[VD_*E_], g_wak[AD_*E_], g_wvv[VD_*E_], g_wav[AD_*E_];
__device__ __half g_wov[E_*VD_], g_woa[E_*AD_];

__device__ __forceinline__ float ex2f(float x) {
    float r; asm("ex2.approx.f32 %0, %1;" : "=f"(r) : "f"(x)); return r;
}
__device__ __forceinline__ uint32_t cvta_s(const void* p) {
    uint32_t r;
    asm("{ .reg .u64 t; cvta.to.shared.u64 t, %1; cvt.u32.u64 %0, t; }" : "=r"(r) : "l"(p));
    return r;
}
__device__ __forceinline__ uint32_t h2u(float x, float y) {
    __half2 h = __floats2half2_rn(x, y); return *(uint32_t*)&h;
}
__device__ __forceinline__ uint4 pack8h(const float* x) {
    union { __half b[8]; uint4 u; } U;
    #pragma unroll
    for (int j = 0; j < 8; j++) U.b[j] = __float2half_rn(x[j]);
    return U.u;
}
__device__ __forceinline__ void ldsm4(uint32_t& r0, uint32_t& r1, uint32_t& r2, uint32_t& r3,
                                      uint32_t a) {
    asm volatile("ldmatrix.sync.aligned.m8n8.x4.shared.b16 {%0,%1,%2,%3}, [%4];"
                 : "=r"(r0), "=r"(r1), "=r"(r2), "=r"(r3) : "r"(a));
}
__device__ __forceinline__ void ldsm4t(uint32_t& r0, uint32_t& r1, uint32_t& r2, uint32_t& r3,
                                       uint32_t a) {
    asm volatile("ldmatrix.sync.aligned.m8n8.x4.trans.shared.b16 {%0,%1,%2,%3}, [%4];"
                 : "=r"(r0), "=r"(r1), "=r"(r2), "=r"(r3) : "r"(a));
}
__device__ __forceinline__ void mma4(float* c, const uint32_t* a, uint32_t b0, uint32_t b1) {
    asm volatile("mma.sync.aligned.m16n8k16.row.col.f32.f16.f16.f32 "
                 "{%0,%1,%2,%3}, {%4,%5,%6,%7}, {%8,%9}, {%0,%1,%2,%3};"
                 : "+f"(c[0]), "+f"(c[1]), "+f"(c[2]), "+f"(c[3])
                 : "r"(a[0]), "r"(a[1]), "r"(a[2]), "r"(a[3]), "r"(b0), "r"(b1));
}
#define CP16(dst, src) \
    asm volatile("cp.async.cg.shared.global [%0], [%1], 16;" :: "r"(dst), "l"(src))
#define CPCOMMIT() asm volatile("cp.async.commit_group;" ::: "memory")

// ============ f2h_all: all 8 fp32->fp16 conversions in ONE launch ==========
struct CvArgs { const float* s[8]; __half* d[8]; int boff[9]; };

__global__ void __launch_bounds__(256) f2h_all(CvArgs ca)
{
    int bx = blockIdx.x, seg = 0;
    #pragma unroll
    for (int i = 1; i < 8; i++) if (bx >= ca.boff[i]) seg = i;
    size_t li = ((size_t)(bx - ca.boff[seg])*256 + threadIdx.x)*8;
    const float* s = ca.s[seg];
    float x[8];
    *(float4*)x     = *(const float4*)(s+li);
    *(float4*)(x+4) = *(const float4*)(s+li+4);
    *(uint4*)(ca.d[seg]+li) = pack8h(x);
}

// ============ scores_strip: P[s0:+128][all t] = exp2(K @ Q^T) ==============
#define SS_Q  36864
#define SS_SZ 92160

__global__ void __launch_bounds__(256,2) scores_strip()
{
    extern __shared__ char sm[];
    const uint32_t smb = cvta_s(sm);
    __half* PS = (__half*)sm;

    const int tid = threadIdx.x, w = tid>>5, lane = tid&31;
    const int gid = lane>>2, tig = lane&3, wq = lane&7;
    const int wm = w&3, wn = w>>2;
    const int bh = blockIdx.y;
    const int s0 = blockIdx.x*128;

    {
        const uint4* ks = (const uint4*)(g_k + ((size_t)bh*S_+s0)*64);
        #pragma unroll
        for (int i = 0; i < 4; i++) {
            int q = tid + i*256, r = q>>3, c = q&7;
            *(uint4*)((__half*)sm + r*72 + c*8) = ks[q];
        }
    }
    __syncthreads();
    uint32_t KA[4][2][4];
    #pragma unroll
    for (int ksi = 0; ksi < 4; ksi++)
        #pragma unroll
        for (int i = 0; i < 2; i++) {
            uint32_t ad = smb + (uint32_t)(((wm*32+i*16+(lane&15))*72 + (lane>>4)*8)*2)
                        + ksi*32;
            ldsm4(KA[ksi][i][0], KA[ksi][i][1], KA[ksi][i][2], KA[ksi][i][3], ad);
        }
    __syncthreads();

    auto issueQ = [&](int it, int j) {
        const __half* qs = g_q + ((size_t)bh*T_ + it*128)*64;
        uint32_t base = smb + SS_Q + (uint32_t)(j*18432);
        #pragma unroll
        for (int i = 0; i < 4; i++) {
            int q = tid + i*256, r = q>>3, c = q&7;
            CP16(base + (uint32_t)(r*144 + c*16), qs + (size_t)r*64 + c*8);
        }
        CPCOMMIT();
    };
    issueQ(0, 0); issueQ(1, 1);

    const uint32_t qlo = (uint32_t)((wq + ((lane>>4)&1)*8)*144) + ((lane>>3)&1)*16;

    for (int it = 0; it < 16; it++) {
        if (it < 15) { asm volatile("cp.async.wait_group 1;" ::: "memory"); }
        else         { asm volatile("cp.async.wait_group 0;" ::: "memory"); }
        __syncthreads();
        if (it + 2 < 16) issueQ(it+2, (it+2)%3);

        const uint32_t qb = smb + SS_Q + (uint32_t)((it%3)*18432);
        float acc[2][8][4] = {};
        #pragma unroll
        for (int ksi = 0; ksi < 4; ksi++) {
            #pragma unroll
            for (int jb = 0; jb < 4; jb++) {
                uint32_t q0,q1,q2,q3;
                ldsm4(q0,q1,q2,q3, qb + qlo + (wn*64 + jb*16)*144 + ksi*32);
                #pragma unroll
                for (int i = 0; i < 2; i++) {
                    mma4(acc[i][jb*2],   KA[ksi][i], q0, q1);
                    mma4(acc[i][jb*2+1], KA[ksi][i], q2, q3);
                }
            }
        }
        #pragma unroll
        for (int i = 0; i < 2; i++)
            #pragma unroll
            for (int nf = 0; nf < 8; nf++) {
                int col = wn*64 + nf*8 + 2*tig;
                int r0 = wm*32 + i*16 + gid;
                *(uint32_t*)(PS + r0*136 + col) =
                    h2u(ex2f(acc[i][nf][0]), ex2f(acc[i][nf][1]));
                *(uint32_t*)(PS + (r0+8)*136 + col) =
                    h2u(ex2f(acc[i][nf][2]), ex2f(acc[i][nf][3]));
            }
        __syncthreads();
        {
            int r = tid>>1, c0 = (tid&1)*64;
            const __half* ps = PS + r*136 + c0;
            __half* gp = g_p + ((size_t)(bh*S_+s0+r))*T_ + it*128 + c0;
            #pragma unroll
            for (int i = 0; i < 8; i++)
                *(uint4*)(gp + i*8) = *(const uint4*)(ps + i*8);
        }
        __syncthreads();
    }
}

// ============ gemm_outa: out_a = (P @ vv)/l ; va2 = va/l ===================
#define OA_VB 30720
#define OA_LS 45056
#define OA_SZ 45568

__global__ void __launch_bounds__(256,2) gemm_outa()
{
    extern __shared__ char sm[];
    const uint32_t smb = cvta_s(sm);
    float* lsm = (float*)(sm + OA_LS);
    float* OS  = (float*)sm;

    const int tid = threadIdx.x, w = tid>>5, lane = tid&31;
    const int wm = w&3, wn = w>>2;
    const int gid = lane>>2, tig = lane&3, wq = lane&7;
    const int bh = blockIdx.y, b = bh>>3, h = bh&7;
    const int s0 = blockIdx.x*128;

    const int pr = tid>>1, pc = (tid&1)*16;
    const __half* psrc = g_p + (size_t)(bh*S_ + s0 + pr)*T_ + pc;
    const uint32_t pdst = smb + (uint32_t)(pr*80 + pc*2);
    const int vr = tid>>3, vc = tid&7;
    const __half* vsrc = g_vv + (size_t)bh*T_*64 + (size_t)vr*64 + vc*8;
    const uint32_t vdst = smb + OA_VB + (uint32_t)(vr*144 + vc*16);

    #pragma unroll
    for (int c = 0; c < 2; c++) {
        CP16(pdst + c*10240,      psrc + (size_t)c*32);
        CP16(pdst + c*10240 + 16, psrc + (size_t)c*32 + 8);
        CP16(vdst + c*4608,       vsrc + (size_t)c*32*64);
        CPCOMMIT();
    }

    float acc[2][4][4] = {};
    float lr[2][2] = {};

    for (int c = 0; c < 64; c++) {
        if (c < 63) { asm volatile("cp.async.wait_group 1;" ::: "memory"); }
        else        { asm volatile("cp.async.wait_group 0;" ::: "memory"); }
        __syncthreads();
        if (c + 2 < 64) {
            int j = (c+2)%3;
            CP16(pdst + j*10240,      psrc + (size_t)(c+2)*32);
            CP16(pdst + j*10240 + 16, psrc + (size_t)(c+2)*32 + 8);
            CP16(vdst + j*4608,       vsrc + (size_t)(c+2)*32*64);
            CPCOMMIT();
        }
        const uint32_t pb = smb + (uint32_t)((c%3)*10240);
        const uint32_t vb = smb + OA_VB + (uint32_t)((c%3)*4608);
        #pragma unroll
        for (int ks = 0; ks < 2; ks++) {
            uint32_t aa[2][4];
            #pragma unroll
            for (int i = 0; i < 2; i++) {
                uint32_t ad = pb + (uint32_t)(((wm*32+i*16+(lane&15))*40
                             + ks*16 + (lane>>4)*8)*2);
                ldsm4(aa[i][0], aa[i][1], aa[i][2], aa[i][3], ad);
                if (wn == 0) {
                    float2 f0 = __half22float2(*(__half2*)&aa[i][0]);
                    float2 f2 = __half22float2(*(__half2*)&aa[i][2]);
                    float2 f1 = __half22float2(*(__half2*)&aa[i][1]);
                    float2 f3 = __half22float2(*(__half2*)&aa[i][3]);
                    lr[i][0] += f0.x+f0.y+f2.x+f2.y;
                    lr[i][1] += f1.x+f1.y+f3.x+f3.y;
                }
            }
            #pragma unroll
            for (int jn = 0; jn < 2; jn++) {
                uint32_t v0,v1,v2,v3;
                uint32_t bd = vb + (uint32_t)((ks*16 + wq + ((lane>>3)&1)*8)*144)
                            + (uint32_t)((wn*32 + jn*16)*2) + ((lane>>4)&1)*16;
                ldsm4t(v0,v1,v2,v3, bd);
                #pragma unroll
                for (int i = 0; i < 2; i++) {
                    mma4(acc[i][2*jn],   aa[i], v0, v1);
                    mma4(acc[i][2*jn+1], aa[i], v2, v3);
                }
            }
        }
        __syncthreads();
    }

    #pragma unroll
    for (int i = 0; i < 2; i++)
        #pragma unroll
        for (int hh2 = 0; hh2 < 2; hh2++) {
            lr[i][hh2] += __shfl_xor_sync(0xffffffffu, lr[i][hh2], 1);
            lr[i][hh2] += __shfl_xor_sync(0xffffffffu, lr[i][hh2], 2);
        }
    if (wn == 0 && tig == 0) {
        #pragma unroll
        for (int i = 0; i < 2; i++) {
            lsm[wm*32 + i*16 + gid]     = lr[i][0];
            lsm[wm*32 + i*16 + gid + 8] = lr[i][1];
        }
    }
    __syncthreads();
    {
        #pragma unroll
        for (int i = 0; i < 2; i++) {
            int r0 = wm*32 + i*16 + gid;
            float inv0 = 1.0f/lsm[r0], inv1 = 1.0f/lsm[r0+8];
            #pragma unroll
            for (int nf = 0; nf < 4; nf++) {
                int cb = wn*32 + nf*8 + 2*tig;
                OS[r0*68 + cb]       = acc[i][nf][0]*inv0;
                OS[r0*68 + cb + 1]   = acc[i][nf][1]*inv0;
                OS[(r0+8)*68 + cb]   = acc[i][nf][2]*inv1;
                OS[(r0+8)*68 + cb+1] = acc[i][nf][3]*inv1;
            }
        }
    }
    __syncthreads();
    {
        int r = tid>>1, c0 = (tid&1)*32;
        float inv = 1.0f/lsm[r];
        float x[32];
        const float* row = OS + r*68 + c0;
        #pragma unroll
        for (int g4 = 0; g4 < 8; g4++) *(float4*)(x+g4*4) = *(const float4*)(row+g4*4);
        size_t o = ((size_t)(b*S_+s0+r))*E_ + h*64 + c0;
        #pragma unroll
        for (int g8 = 0; g8 < 4; g8++)
            *(uint4*)(g_oa + o + g8*8) = pack8h(x + g8*8);
        size_t vi = ((size_t)(bh*S_+s0+r))*64 + c0;
        #pragma unroll
        for (int g8 = 0; g8 < 4; g8++) {
            uint4 wv = *(uint4*)(g_va + vi + g8*8);
            const __half* hp = (const __half*)&wv;
            float y[8];
            #pragma unroll
            for (int j = 0; j < 8; j++) y[j] = __half2float(hp[j]) * inv;
            *(uint4*)(g_v2 + vi + g8*8) = pack8h(y);
        }
    }
}

// ============ gemm_outv: out_v = P^T @ va2 (K=512) =========================
#define FV_AB 26112
#define FV_SZ 39936

__global__ void __launch_bounds__(256,2) gemm_outv()
{
    extern __shared__ char sm[];
    const uint32_t smb = cvta_s(sm);
    float* OS = (float*)sm;

    const int tid = threadIdx.x, w = tid>>5, lane = tid&31;
    const int wm = w&3, wn = w>>2;
    const int gid = lane>>2, tig = lane&3;
    const int bh = blockIdx.y, b = bh>>3, h = bh&7;
    const int t0 = blockIdx.x*128;

    const int cr = tid>>3, cc = tid&7;
    const __half* psrc = g_p  + (size_t)(bh*S_ + cr)*T_ + t0 + cc*8;
    const __half* asrc = g_v2 + (size_t)(bh*S_ + cr)*64 + cc*8;
    const uint32_t pdst = smb + (uint32_t)(cr*272 + cc*16);
    const uint32_t adst = smb + FV_AB + (uint32_t)(cr*144 + cc*16);

    #pragma unroll
    for (int c = 0; c < 2; c++) {
        CP16(pdst + c*8704,       psrc + (size_t)c*32*T_);
        CP16(pdst + c*8704 + 128, psrc + (size_t)c*32*T_ + 64);
        CP16(adst + c*4608,       asrc + (size_t)c*32*64);
        CPCOMMIT();
    }

    float acc[2][4][4] = {};

    for (int c = 0; c < 16; c++) {
        if (c < 15) { asm volatile("cp.async.wait_group 1;" ::: "memory"); }
        else        { asm volatile("cp.async.wait_group 0;" ::: "memory"); }
        __syncthreads();
        if (c + 2 < 16) {
            int j = (c+2)%3;
            CP16(pdst + j*8704,       psrc + (size_t)(c+2)*32*T_);
            CP16(pdst + j*8704 + 128, psrc + (size_t)(c+2)*32*T_ + 64);
            CP16(adst + j*4608,       asrc + (size_t)(c+2)*32*64);
            CPCOMMIT();
        }
        const uint32_t pb = smb + (uint32_t)((c%3)*8704);
        const uint32_t ab = smb + FV_AB + (uint32_t)((c%3)*4608);
        #pragma unroll
        for (int ks = 0; ks < 2; ks++) {
            uint32_t aa[2][4];
            #pragma unroll
            for (int i = 0; i < 2; i++) {
                uint32_t ad = pb + (uint32_t)(((ks*16 + (lane&7) + ((lane>>4)&1)*8)*136
                              + wm*32 + i*16 + ((lane>>3)&1)*8)*2);
                ldsm4t(aa[i][0], aa[i][1], aa[i][2], aa[i][3], ad);
            }
            #pragma unroll
            for (int jn = 0; jn < 2; jn++) {
                uint32_t v0,v1,v2,v3;
                uint32_t bd = ab + (uint32_t)(((ks*16 + (lane&7) + ((lane>>3)&1)*8)*72
                              + wn*32 + jn*16 + ((lane>>4)&1)*8)*2);
                ldsm4t(v0,v1,v2,v3, bd);
                #pragma unroll
                for (int i = 0; i < 2; i++) {
                    mma4(acc[i][2*jn],   aa[i], v0, v1);
                    mma4(acc[i][2*jn+1], aa[i], v2, v3);
                }
            }
        }
        __syncthreads();
    }
    {
        #pragma unroll
        for (int i = 0; i < 2; i++)
            #pragma unroll
            for (int nf = 0; nf < 4; nf++) {
                int rr = wm*32 + i*16 + gid, cbase = wn*32 + nf*8 + 2*tig;
                OS[rr*68 + cbase]       = acc[i][nf][0];
                OS[rr*68 + cbase + 1]   = acc[i][nf][1];
                OS[(rr+8)*68 + cbase]   = acc[i][nf][2];
                OS[(rr+8)*68 + cbase+1] = acc[i][nf][3];
            }
    }
    __syncthreads();
    {
        int r = tid>>1, c0 = (tid&1)*32;
        float x[32];
        const float* row = OS + r*68 + c0;
        #pragma unroll
        for (int g4 = 0; g4 < 8; g4++) *(float4*)(x+g4*4) = *(const float4*)(row+g4*4);
        size_t o = ((size_t)(b*T_+t0+r))*E_ + h*64 + c0;
        #pragma unroll
        for (int g8 = 0; g8 < 4; g8++)
            *(uint4*)(g_ov + o + g8*8) = pack8h(x + g8*8);
    }
}

// ============ pipelined fp16 projection (128x128 tile, KC=32) ==============
#define PJ_BUF 18944
#define PJ_SZ  56832

template<int OP>
__device__ __forceinline__ void proj_body(
    const __half* Ap, const __half* Wp, const float* bias, float* C, __half* Dh,
    int K, int N, int m0, int n0, float alpha, int lsh)
{
    extern __shared__ char sm[];
    const uint32_t smb = cvta_s(sm);
    const int tid = threadIdx.x, w = tid>>5, lane = tid&31;
    const int wm = w&3, wn = w>>2;
    const int gid = lane>>2, tig = lane&3, wq = lane&7;

    float acc[2][8][4] = {};
    const int nc = K >> 5;

    auto issue = [&](int c, int j) {
        const int k0 = c*32;
        uint32_t base = smb + (uint32_t)(j*PJ_BUF);
        #pragma unroll
        for (int i = 0; i < 2; i++) {
            int idx = tid + i*256, r = idx>>2, c4 = idx&3;
            CP16(base + (uint32_t)(r*80 + c4*16),
                 Ap + (size_t)(m0+r)*K + k0 + c4*8);
        }
        #pragma unroll
        for (int i = 0; i < 2; i++) {
            int idx = tid + i*256, k = idx>>4, n8 = idx&15;
            CP16(base + 10240 + (uint32_t)(k*272 + n8*16),
                 Wp + (size_t)(k0+k)*N + n0 + n8*8);
        }
        CPCOMMIT();
    };
    issue(0, 0); issue(1, 1);

    for (int c = 0; c < nc; c++) {
        if (c < nc-1) { asm volatile("cp.async.wait_group 1;" ::: "memory"); }
        else          { asm volatile("cp.async.wait_group 0;" ::: "memory"); }
        __syncthreads();
        if (c + 2 < nc) issue(c+2, (c+2)%3);
        const uint32_t pb = smb + (uint32_t)((c%3)*PJ_BUF);
        #pragma unroll
        for (int ks = 0; ks < 2; ks++) {
            uint32_t ah[2][4];
            #pragma unroll
            for (int i = 0; i < 2; i++) {
                uint32_t ad = pb + (uint32_t)(((wm*32+i*16+(lane&15))*40
                             + ks*16 + (lane>>4)*8)*2);
                ldsm4(ah[i][0], ah[i][1], ah[i][2], ah[i][3], ad);
            }
            #pragma unroll
            for (int g = 0; g < 4; g++) {
                uint32_t bd = pb + 10240
                    + (uint32_t)((ks*16 + wq + ((lane>>3)&1)*8)*272)
                    + (uint32_t)((wn*64 + g*16)*2) + ((lane>>4)&1)*16;
                uint32_t b0,b1,b2,b3;
                ldsm4t(b0,b1,b2,b3, bd);
                #pragma unroll
                for (int i = 0; i < 2; i++) {
                    mma4(acc[i][2*g],   ah[i], b0, b1);
                    mma4(acc[i][2*g+1], ah[i], b2, b3);
                }
            }
        }
        __syncthreads();
    }

    float* OS = (float*)sm;
    #pragma unroll
    for (int hf = 0; hf < 2; hf++) {
        __syncthreads();
        if (wn == hf) {
            #pragma unroll
            for (int i = 0; i < 2; i++)
                #pragma unroll
                for (int nf = 0; nf < 8; nf++) {
                    int r0 = wm*32 + i*16 + gid, cb = nf*8 + 2*tig;
                    OS[r0*68 + cb]       = acc[i][nf][0];
                    OS[r0*68 + cb + 1]   = acc[i][nf][1];
                    OS[(r0+8)*68 + cb]   = acc[i][nf][2];
                    OS[(r0+8)*68 + cb+1] = acc[i][nf][3];
                }
        }
        __syncthreads();
        const int r = tid>>1, c0 = (tid&1)*32;
        const int nbase = n0 + hf*64;
        if (OP == 0) {
            const int Lm1 = (1 << lsh) - 1;
            int m = m0 + r, bb = m >> lsh, tok = m & Lm1;
            int hh = nbase >> 6;
            size_t o = (((size_t)(bb*H_ + hh) << lsh) + tok) * 64 + c0;
            #pragma unroll
            for (int g8 = 0; g8 < 4; g8++) {
                float x[8];
                #pragma unroll
                for (int j = 0; j < 8; j++)
                    x[j] = alpha * (OS[r*68 + c0 + g8*8 + j]
                                    + __ldg(bias + nbase + c0 + g8*8 + j));
                *(uint4*)(Dh + o + g8*8) = pack8h(x);
            }
        } else {
            float* crow = C + (size_t)(m0+r)*N + nbase + c0;
            #pragma unroll
            for (int g4 = 0; g4 < 8; g4++) {
                float4 v;
                v.x = OS[r*68 + c0 + g4*4 + 0] + __ldg(bias + nbase + c0 + g4*4 + 0);
                v.y = OS[r*68 + c0 + g4*4 + 1] + __ldg(bias + nbase + c0 + g4*4 + 1);
                v.z = OS[r*68 + c0 + g4*4 + 2] + __ldg(bias + nbase + c0 + g4*4 + 2);
                v.w = OS[r*68 + c0 + g4*4 + 3] + __ldg(bias + nbase + c0 + g4*4 + 3);
                *(float4*)(crow + g4*4) = v;
            }
        }
    }
}

// all 4 input projections in ONE launch: y<128 -> v-side (K=512), else a-side
struct PIArgs {
    const float *bvq, *bvv, *bak, *bav;
    float alq;
};
__global__ void __launch_bounds__(256,2) proj_in_all(PIArgs p)
{
    const int sel = blockIdx.x >> 2;
    if (blockIdx.y < 128) {
        proj_body<0>(g_vh, sel ? g_wvv : g_wvq, sel ? p.bvv : p.bvq, 0,
                     sel ? g_vv : g_q,
                     VD_, 512, blockIdx.y*128, (blockIdx.x & 3)*128,
                     sel ? 1.0f : p.alq, 11);
    } else {
        proj_body<0>(g_ah, sel ? g_wav : g_wak, sel ? p.bav : p.bak, 0,
                     sel ? g_va : g_k,
                     AD_, 512, (blockIdx.y-128)*128, (blockIdx.x & 3)*128,
                     1.0f, 9);
    }
}

__global__ void __launch_bounds__(256,2) proj_out2(
    const float* b1, float* C1, const float* b2, float* C2)
{
    const bool r2 = blockIdx.y >= 128;
    if (r2 && blockIdx.x >= 2) return;
    proj_body<1>(r2 ? g_oa : g_ov, r2 ? g_woa : g_wov,
                 r2 ? b2 : b1, r2 ? C2 : C1, 0,
                 512, r2 ? 256 : 512,
                 (r2 ? blockIdx.y - 128 : blockIdx.y)*128, blockIdx.x*128,
                 1.0f, 0);
}

// ---------------------------------------------------------------------------
extern "C" void kernel_launch(void* const* d_in, const int* in_sizes, int n_in,
                              void* d_out, int out_size)
{
    const float* v    = (const float*)d_in[0];
    const float* a    = (const float*)d_in[1];
    const float* w_vq = (const float*)d_in[2];
    const float* b_vq = (const float*)d_in[3];
    const float* w_ak = (const float*)d_in[4];
    const float* b_ak = (const float*)d_in[5];
    const float* w_vv = (const float*)d_in[6];
    const float* b_vv = (const float*)d_in[7];
    const float* w_av = (const float*)d_in[8];
    const float* b_av = (const float*)d_in[9];
    const float* w_ov = (const float*)d_in[10];
    const float* b_ov = (const float*)d_in[11];
    const float* w_oa = (const float*)d_in[12];
    const float* b_oa = (const float*)d_in[13];
    float* out = (float*)d_out;

    __half *vh, *ah, *wvq, *wak, *wvv, *wav, *wov, *woa;
    cudaGetSymbolAddress((void**)&vh,  g_vh);  cudaGetSymbolAddress((void**)&ah,  g_ah);
    cudaGetSymbolAddress((void**)&wvq, g_wvq); cudaGetSymbolAddress((void**)&wak, g_wak);
    cudaGetSymbolAddress((void**)&wvv, g_wvv); cudaGetSymbolAddress((void**)&wav, g_wav);
    cudaGetSymbolAddress((void**)&wov, g_wov); cudaGetSymbolAddress((void**)&woa, g_woa);

    cudaFuncSetAttribute(proj_in_all, cudaFuncAttributeMaxDynamicSharedMemorySize, PJ_SZ);
    cudaFuncSetAttribute(proj_out2,   cudaFuncAttributeMaxDynamicSharedMemorySize, PJ_SZ);
    cudaFuncSetAttribute(scores_strip, cudaFuncAttributeMaxDynamicSharedMemorySize, SS_SZ);
    cudaFuncSetAttribute(gemm_outa, cudaFuncAttributeMaxDynamicSharedMemorySize, OA_SZ);
    cudaFuncSetAttribute(gemm_outv, cudaFuncAttributeMaxDynamicSharedMemorySize, FV_SZ);

    // one conversion launch: segment table (block counts = elems/2048)
    CvArgs ca;
    const float* srcs[8] = { v, a, w_vq, w_ak, w_vv, w_av, w_ov, w_oa };
    __half* dsts[8]      = { vh, ah, wvq, wak, wvv, wav, wov, woa };
    int nblk[8] = { B_*T_*VD_/2048, B_*S_*AD_/2048,
                    VD_*E_/2048, AD_*E_/2048, VD_*E_/2048, AD_*E_/2048,
                    E_*VD_/2048, E_*AD_/2048 };
    int acc0 = 0;
    for (int i = 0; i < 8; i++) { ca.s[i] = srcs[i]; ca.d[i] = dsts[i];
                                  ca.boff[i] = acc0; acc0 += nblk[i]; }
    ca.boff[8] = acc0;
    f2h_all<<<acc0, 256>>>(ca);

    PIArgs pa{ b_vq, b_vv, b_ak, b_av, 0.125f * 1.4426950408889634f };
    proj_in_all<<<dim3(8,160), 256, PJ_SZ>>>(pa);

    scores_strip<<<dim3(4, BH_), 256, SS_SZ>>>();
    gemm_outa<<<dim3(S_/128, BH_), 256, OA_SZ>>>();
    gemm_outv<<<dim3(T_/128, BH_), 256, FV_SZ>>>();

    proj_out2<<<dim3(4,160), 256, PJ_SZ>>>(b_ov, out,
                                           b_oa, out + (size_t)B_*T_*VD_);
}

// round 17
// speedup vs baseline: 2.3775x; 1.1487x over previous
#include <cuda_runtime.h>
#include <cuda_fp16.h>
#include <cstdint>

#define B_ 8
#define T_ 2048
#define S_ 512
#define VD_ 512
#define AD_ 256
#define E_ 512
#define H_ 8
#define BH_ 64

__device__ __half g_q [(size_t)BH_*T_*64];
__device__ __half g_k [(size_t)BH_*S_*64];
__device__ __half g_vv[(size_t)BH_*T_*64];
__device__ __half g_va[(size_t)BH_*S_*64];
__device__ __half g_v2[(size_t)BH_*S_*64];          // va / l
__device__ __half g_p [(size_t)BH_*S_*T_];          // exp2(S) fp16
__device__ __half g_ov[(size_t)B_*T_*E_];
__device__ __half g_oa[(size_t)B_*S_*E_];
__device__ __half g_vh [(size_t)B_*T_*VD_];
__device__ __half g_ah [(size_t)B_*S_*AD_];
__device__ __half g_wvq[VD_*E_], g_wak[AD_*E_], g_wvv[VD_*E_], g_wav[AD_*E_];
__device__ __half g_wov[E_*VD_], g_woa[E_*AD_];

__device__ __forceinline__ float ex2f(float x) {
    float r; asm("ex2.approx.f32 %0, %1;" : "=f"(r) : "f"(x)); return r;
}
__device__ __forceinline__ uint32_t cvta_s(const void* p) {
    uint32_t r;
    asm("{ .reg .u64 t; cvta.to.shared.u64 t, %1; cvt.u32.u64 %0, t; }" : "=r"(r) : "l"(p));
    return r;
}
__device__ __forceinline__ uint32_t h2u(float x, float y) {
    __half2 h = __floats2half2_rn(x, y); return *(uint32_t*)&h;
}
__device__ __forceinline__ uint4 pack8h(const float* x) {
    union { __half b[8]; uint4 u; } U;
    #pragma unroll
    for (int j = 0; j < 8; j++) U.b[j] = __float2half_rn(x[j]);
    return U.u;
}
__device__ __forceinline__ void ldsm4(uint32_t& r0, uint32_t& r1, uint32_t& r2, uint32_t& r3,
                                      uint32_t a) {
    asm volatile("ldmatrix.sync.aligned.m8n8.x4.shared.b16 {%0,%1,%2,%3}, [%4];"
                 : "=r"(r0), "=r"(r1), "=r"(r2), "=r"(r3) : "r"(a));
}
__device__ __forceinline__ void ldsm4t(uint32_t& r0, uint32_t& r1, uint32_t& r2, uint32_t& r3,
                                       uint32_t a) {
    asm volatile("ldmatrix.sync.aligned.m8n8.x4.trans.shared.b16 {%0,%1,%2,%3}, [%4];"
                 : "=r"(r0), "=r"(r1), "=r"(r2), "=r"(r3) : "r"(a));
}
__device__ __forceinline__ void mma4(float* c, const uint32_t* a, uint32_t b0, uint32_t b1) {
    asm volatile("mma.sync.aligned.m16n8k16.row.col.f32.f16.f16.f32 "
                 "{%0,%1,%2,%3}, {%4,%5,%6,%7}, {%8,%9}, {%0,%1,%2,%3};"
                 : "+f"(c[0]), "+f"(c[1]), "+f"(c[2]), "+f"(c[3])
                 : "r"(a[0]), "r"(a[1]), "r"(a[2]), "r"(a[3]), "r"(b0), "r"(b1));
}
#define CP16(dst, src) \
    asm volatile("cp.async.cg.shared.global [%0], [%1], 16;" :: "r"(dst), "l"(src))
#define CPCOMMIT() asm volatile("cp.async.commit_group;" ::: "memory")

// ============ f2h_all: all 8 fp32->fp16 conversions in ONE launch ==========
struct CvArgs { const float* s[8]; __half* d[8]; int boff[9]; };

__global__ void __launch_bounds__(256) f2h_all(CvArgs ca)
{
    int bx = blockIdx.x, seg = 0;
    #pragma unroll
    for (int i = 1; i < 8; i++) if (bx >= ca.boff[i]) seg = i;
    size_t li = ((size_t)(bx - ca.boff[seg])*256 + threadIdx.x)*8;
    const float* s = ca.s[seg];
    float x[8];
    *(float4*)x     = *(const float4*)(s+li);
    *(float4*)(x+4) = *(const float4*)(s+li+4);
    *(uint4*)(ca.d[seg]+li) = pack8h(x);
}

// ============ scores_outa: fused P=exp2(K@Q^T) -> g_p AND out_a=(P@vv)/l ===
// Per (s-strip 128, bh). t-chunks of 64; ring = 3 x (Q 9216B + VV 9216B).
// PS tile 128x72 halves at 0. lsm at 73728. OS (epilogue) reuses base.
#define SO_R0 18432
#define SO_LS 73728
#define SO_SZ 75264

__global__ void __launch_bounds__(256,2) scores_outa()
{
    extern __shared__ char sm[];
    const uint32_t smb = cvta_s(sm);
    __half* PS  = (__half*)sm;
    float* lsm  = (float*)(sm + SO_LS);
    float* linv = lsm + 256;
    float* OS   = (float*)sm;

    const int tid = threadIdx.x, w = tid>>5, lane = tid&31;
    const int gid = lane>>2, tig = lane&3, wq = lane&7;
    const int wm = w&3, wn = w>>2;
    const int bh = blockIdx.y, b = bh>>3, h = bh&7;
    const int s0 = blockIdx.x*128;

    // K tile 128x64 -> smem (stride 72 halves), then register fragments
    {
        const uint4* ks = (const uint4*)(g_k + ((size_t)bh*S_+s0)*64);
        #pragma unroll
        for (int i = 0; i < 4; i++) {
            int q = tid + i*256, r = q>>3, c = q&7;
            *(uint4*)((__half*)sm + r*72 + c*8) = ks[q];
        }
    }
    __syncthreads();
    uint32_t KA[4][2][4];
    #pragma unroll
    for (int ksi = 0; ksi < 4; ksi++)
        #pragma unroll
        for (int i = 0; i < 2; i++) {
            uint32_t ad = smb + (uint32_t)(((wm*32+i*16+(lane&15))*72 + (lane>>4)*8)*2)
                        + ksi*32;
            ldsm4(KA[ksi][i][0], KA[ksi][i][1], KA[ksi][i][2], KA[ksi][i][3], ad);
        }
    __syncthreads();

    // ring: Q chunk 64x64 + VV chunk 64x64, both stride 72 halves (144 B)
    auto issueQV = [&](int it, int j) {
        const __half* qs = g_q  + ((size_t)bh*T_ + it*64)*64;
        const __half* vs = g_vv + ((size_t)bh*T_ + it*64)*64;
        uint32_t base = smb + SO_R0 + (uint32_t)(j*18432);
        #pragma unroll
        for (int i = 0; i < 2; i++) {
            int q = tid + i*256, r = q>>3, c = q&7;
            CP16(base + (uint32_t)(r*144 + c*16),        qs + (size_t)r*64 + c*8);
            CP16(base + 9216 + (uint32_t)(r*144 + c*16), vs + (size_t)r*64 + c*8);
        }
        CPCOMMIT();
    };
    issueQV(0, 0); issueQV(1, 1);

    const uint32_t qlo = (uint32_t)((wq + ((lane>>4)&1)*8)*144) + ((lane>>3)&1)*16;
    float accv[2][4][4] = {};
    float lr[2][2] = {};

    for (int it = 0; it < 32; it++) {
        if (it < 31) { asm volatile("cp.async.wait_group 1;" ::: "memory"); }
        else         { asm volatile("cp.async.wait_group 0;" ::: "memory"); }
        __syncthreads();
        if (it + 2 < 32) issueQV(it+2, (it+2)%3);

        const uint32_t qb = smb + SO_R0 + (uint32_t)((it%3)*18432);
        const uint32_t vb = qb + 9216;

        // ---- S = K @ Q^T (64 t cols; wn covers 32, jb 2x16) ----
        float acc[2][4][4] = {};
        #pragma unroll
        for (int ksi = 0; ksi < 4; ksi++) {
            #pragma unroll
            for (int jb = 0; jb < 2; jb++) {
                uint32_t q0,q1,q2,q3;
                ldsm4(q0,q1,q2,q3, qb + qlo + (wn*32 + jb*16)*144 + ksi*32);
                #pragma unroll
                for (int i = 0; i < 2; i++) {
                    mma4(acc[i][jb*2],   KA[ksi][i], q0, q1);
                    mma4(acc[i][jb*2+1], KA[ksi][i], q2, q3);
                }
            }
        }
        // ---- ex2 + l accumulation + pack -> PS (stride 72 halves) ----
        #pragma unroll
        for (int i = 0; i < 2; i++)
            #pragma unroll
            for (int nf = 0; nf < 4; nf++) {
                int col = wn*32 + nf*8 + 2*tig;
                int r0 = wm*32 + i*16 + gid;
                float e0 = ex2f(acc[i][nf][0]), e1 = ex2f(acc[i][nf][1]);
                float e2 = ex2f(acc[i][nf][2]), e3 = ex2f(acc[i][nf][3]);
                lr[i][0] += e0 + e1;
                lr[i][1] += e2 + e3;
                *(uint32_t*)(PS + r0*72 + col)     = h2u(e0, e1);
                *(uint32_t*)(PS + (r0+8)*72 + col) = h2u(e2, e3);
            }
        __syncthreads();
        // ---- accv += P @ vv  (A: PS rows, B: VV ldsm4t) ----
        #pragma unroll
        for (int ks = 0; ks < 4; ks++) {
            uint32_t aa[2][4];
            #pragma unroll
            for (int i = 0; i < 2; i++) {
                uint32_t ad = smb + (uint32_t)(((wm*32+i*16+(lane&15))*72
                             + ks*16 + (lane>>4)*8)*2);
                ldsm4(aa[i][0], aa[i][1], aa[i][2], aa[i][3], ad);
            }
            #pragma unroll
            for (int jn = 0; jn < 2; jn++) {
                uint32_t v0,v1,v2,v3;
                uint32_t bd = vb + (uint32_t)((ks*16 + wq + ((lane>>3)&1)*8)*144)
                            + (uint32_t)((wn*32 + jn*16)*2) + ((lane>>4)&1)*16;
                ldsm4t(v0,v1,v2,v3, bd);
                #pragma unroll
                for (int i = 0; i < 2; i++) {
                    mma4(accv[i][2*jn],   aa[i], v0, v1);
                    mma4(accv[i][2*jn+1], aa[i], v2, v3);
                }
            }
        }
        // ---- coalesced P store (128 rows x 64 halves) ----
        {
            int r = tid>>1, c0 = (tid&1)*32;
            const __half* ps = PS + r*72 + c0;
            __half* gp = g_p + ((size_t)(bh*S_+s0+r))*T_ + it*64 + c0;
            uint4 u0 = *(uint4*)ps, u1 = *(uint4*)(ps+8),
                  u2 = *(uint4*)(ps+16), u3 = *(uint4*)(ps+24);
            *(uint4*)gp = u0; *(uint4*)(gp+8) = u1;
            *(uint4*)(gp+16) = u2; *(uint4*)(gp+24) = u3;
        }
    }
    __syncthreads();

    // ---- l reduction: over tig (shfl), then over wn (smem) ----
    #pragma unroll
    for (int i = 0; i < 2; i++)
        #pragma unroll
        for (int hh2 = 0; hh2 < 2; hh2++) {
            lr[i][hh2] += __shfl_xor_sync(0xffffffffu, lr[i][hh2], 1);
            lr[i][hh2] += __shfl_xor_sync(0xffffffffu, lr[i][hh2], 2);
        }
    if (tig == 0) {
        #pragma unroll
        for (int i = 0; i < 2; i++) {
            lsm[wn*128 + wm*32 + i*16 + gid]     = lr[i][0];
            lsm[wn*128 + wm*32 + i*16 + gid + 8] = lr[i][1];
        }
    }
    __syncthreads();
    if (tid < 128) linv[tid] = 1.0f / (lsm[tid] + lsm[128 + tid]);
    __syncthreads();

    // ---- epilogue: out_a = accv * linv -> g_oa; va2 = va * linv -> g_v2 ----
    {
        #pragma unroll
        for (int i = 0; i < 2; i++) {
            int r0 = wm*32 + i*16 + gid;
            float inv0 = linv[r0], inv1 = linv[r0+8];
            #pragma unroll
            for (int nf = 0; nf < 4; nf++) {
                int cb = wn*32 + nf*8 + 2*tig;
                OS[r0*68 + cb]       = accv[i][nf][0]*inv0;
                OS[r0*68 + cb + 1]   = accv[i][nf][1]*inv0;
                OS[(r0+8)*68 + cb]   = accv[i][nf][2]*inv1;
                OS[(r0+8)*68 + cb+1] = accv[i][nf][3]*inv1;
            }
        }
    }
    __syncthreads();
    {
        int r = tid>>1, c0 = (tid&1)*32;
        float inv = linv[r];
        float x[32];
        const float* row = OS + r*68 + c0;
        #pragma unroll
        for (int g4 = 0; g4 < 8; g4++) *(float4*)(x+g4*4) = *(const float4*)(row+g4*4);
        size_t o = ((size_t)(b*S_+s0+r))*E_ + h*64 + c0;
        #pragma unroll
        for (int g8 = 0; g8 < 4; g8++)
            *(uint4*)(g_oa + o + g8*8) = pack8h(x + g8*8);
        size_t vi = ((size_t)(bh*S_+s0+r))*64 + c0;
        #pragma unroll
        for (int g8 = 0; g8 < 4; g8++) {
            uint4 wv = *(uint4*)(g_va + vi + g8*8);
            const __half* hp = (const __half*)&wv;
            float y[8];
            #pragma unroll
            for (int j = 0; j < 8; j++) y[j] = __half2float(hp[j]) * inv;
            *(uint4*)(g_v2 + vi + g8*8) = pack8h(y);
        }
    }
}

// ============ gemm_outv: out_v = P^T @ va2 (K=512) =========================
#define FV_AB 26112
#define FV_SZ 39936

__global__ void __launch_bounds__(256,2) gemm_outv()
{
    extern __shared__ char sm[];
    const uint32_t smb = cvta_s(sm);
    float* OS = (float*)sm;

    const int tid = threadIdx.x, w = tid>>5, lane = tid&31;
    const int wm = w&3, wn = w>>2;
    const int gid = lane>>2, tig = lane&3;
    const int bh = blockIdx.y, b = bh>>3, h = bh&7;
    const int t0 = blockIdx.x*128;

    const int cr = tid>>3, cc = tid&7;
    const __half* psrc = g_p  + (size_t)(bh*S_ + cr)*T_ + t0 + cc*8;
    const __half* asrc = g_v2 + (size_t)(bh*S_ + cr)*64 + cc*8;
    const uint32_t pdst = smb + (uint32_t)(cr*272 + cc*16);
    const uint32_t adst = smb + FV_AB + (uint32_t)(cr*144 + cc*16);

    #pragma unroll
    for (int c = 0; c < 2; c++) {
        CP16(pdst + c*8704,       psrc + (size_t)c*32*T_);
        CP16(pdst + c*8704 + 128, psrc + (size_t)c*32*T_ + 64);
        CP16(adst + c*4608,       asrc + (size_t)c*32*64);
        CPCOMMIT();
    }

    float acc[2][4][4] = {};

    for (int c = 0; c < 16; c++) {
        if (c < 15) { asm volatile("cp.async.wait_group 1;" ::: "memory"); }
        else        { asm volatile("cp.async.wait_group 0;" ::: "memory"); }
        __syncthreads();
        if (c + 2 < 16) {
            int j = (c+2)%3;
            CP16(pdst + j*8704,       psrc + (size_t)(c+2)*32*T_);
            CP16(pdst + j*8704 + 128, psrc + (size_t)(c+2)*32*T_ + 64);
            CP16(adst + j*4608,       asrc + (size_t)(c+2)*32*64);
            CPCOMMIT();
        }
        const uint32_t pb = smb + (uint32_t)((c%3)*8704);
        const uint32_t ab = smb + FV_AB + (uint32_t)((c%3)*4608);
        #pragma unroll
        for (int ks = 0; ks < 2; ks++) {
            uint32_t aa[2][4];
            #pragma unroll
            for (int i = 0; i < 2; i++) {
                uint32_t ad = pb + (uint32_t)(((ks*16 + (lane&7) + ((lane>>4)&1)*8)*136
                              + wm*32 + i*16 + ((lane>>3)&1)*8)*2);
                ldsm4t(aa[i][0], aa[i][1], aa[i][2], aa[i][3], ad);
            }
            #pragma unroll
            for (int jn = 0; jn < 2; jn++) {
                uint32_t v0,v1,v2,v3;
                uint32_t bd = ab + (uint32_t)(((ks*16 + (lane&7) + ((lane>>3)&1)*8)*72
                              + wn*32 + jn*16 + ((lane>>4)&1)*8)*2);
                ldsm4t(v0,v1,v2,v3, bd);
                #pragma unroll
                for (int i = 0; i < 2; i++) {
                    mma4(acc[i][2*jn],   aa[i], v0, v1);
                    mma4(acc[i][2*jn+1], aa[i], v2, v3);
                }
            }
        }
        __syncthreads();
    }
    {
        #pragma unroll
        for (int i = 0; i < 2; i++)
            #pragma unroll
            for (int nf = 0; nf < 4; nf++) {
                int rr = wm*32 + i*16 + gid, cbase = wn*32 + nf*8 + 2*tig;
                OS[rr*68 + cbase]       = acc[i][nf][0];
                OS[rr*68 + cbase + 1]   = acc[i][nf][1];
                OS[(rr+8)*68 + cbase]   = acc[i][nf][2];
                OS[(rr+8)*68 + cbase+1] = acc[i][nf][3];
            }
    }
    __syncthreads();
    {
        int r = tid>>1, c0 = (tid&1)*32;
        float x[32];
        const float* row = OS + r*68 + c0;
        #pragma unroll
        for (int g4 = 0; g4 < 8; g4++) *(float4*)(x+g4*4) = *(const float4*)(row+g4*4);
        size_t o = ((size_t)(b*T_+t0+r))*E_ + h*64 + c0;
        #pragma unroll
        for (int g8 = 0; g8 < 4; g8++)
            *(uint4*)(g_ov + o + g8*8) = pack8h(x + g8*8);
    }
}

// ============ pipelined fp16 projection (128x128 tile, KC=32) ==============
#define PJ_BUF 18944
#define PJ_SZ  56832

template<int OP>
__device__ __forceinline__ void proj_body(
    const __half* Ap, const __half* Wp, const float* bias, float* C, __half* Dh,
    int K, int N, int m0, int n0, float alpha, int lsh)
{
    extern __shared__ char sm[];
    const uint32_t smb = cvta_s(sm);
    const int tid = threadIdx.x, w = tid>>5, lane = tid&31;
    const int wm = w&3, wn = w>>2;
    const int gid = lane>>2, tig = lane&3, wq = lane&7;

    float acc[2][8][4] = {};
    const int nc = K >> 5;

    auto issue = [&](int c, int j) {
        const int k0 = c*32;
        uint32_t base = smb + (uint32_t)(j*PJ_BUF);
        #pragma unroll
        for (int i = 0; i < 2; i++) {
            int idx = tid + i*256, r = idx>>2, c4 = idx&3;
            CP16(base + (uint32_t)(r*80 + c4*16),
                 Ap + (size_t)(m0+r)*K + k0 + c4*8);
        }
        #pragma unroll
        for (int i = 0; i < 2; i++) {
            int idx = tid + i*256, k = idx>>4, n8 = idx&15;
            CP16(base + 10240 + (uint32_t)(k*272 + n8*16),
                 Wp + (size_t)(k0+k)*N + n0 + n8*8);
        }
        CPCOMMIT();
    };
    issue(0, 0); issue(1, 1);

    for (int c = 0; c < nc; c++) {
        if (c < nc-1) { asm volatile("cp.async.wait_group 1;" ::: "memory"); }
        else          { asm volatile("cp.async.wait_group 0;" ::: "memory"); }
        __syncthreads();
        if (c + 2 < nc) issue(c+2, (c+2)%3);
        const uint32_t pb = smb + (uint32_t)((c%3)*PJ_BUF);
        #pragma unroll
        for (int ks = 0; ks < 2; ks++) {
            uint32_t ah[2][4];
            #pragma unroll
            for (int i = 0; i < 2; i++) {
                uint32_t ad = pb + (uint32_t)(((wm*32+i*16+(lane&15))*40
                             + ks*16 + (lane>>4)*8)*2);
                ldsm4(ah[i][0], ah[i][1], ah[i][2], ah[i][3], ad);
            }
            #pragma unroll
            for (int g = 0; g < 4; g++) {
                uint32_t bd = pb + 10240
                    + (uint32_t)((ks*16 + wq + ((lane>>3)&1)*8)*272)
                    + (uint32_t)((wn*64 + g*16)*2) + ((lane>>4)&1)*16;
                uint32_t b0,b1,b2,b3;
                ldsm4t(b0,b1,b2,b3, bd);
                #pragma unroll
                for (int i = 0; i < 2; i++) {
                    mma4(acc[i][2*g],   ah[i], b0, b1);
                    mma4(acc[i][2*g+1], ah[i], b2, b3);
                }
            }
        }
        __syncthreads();
    }

    float* OS = (float*)sm;
    #pragma unroll
    for (int hf = 0; hf < 2; hf++) {
        __syncthreads();
        if (wn == hf) {
            #pragma unroll
            for (int i = 0; i < 2; i++)
                #pragma unroll
                for (int nf = 0; nf < 8; nf++) {
                    int r0 = wm*32 + i*16 + gid, cb = nf*8 + 2*tig;
                    OS[r0*68 + cb]       = acc[i][nf][0];
                    OS[r0*68 + cb + 1]   = acc[i][nf][1];
                    OS[(r0+8)*68 + cb]   = acc[i][nf][2];
                    OS[(r0+8)*68 + cb+1] = acc[i][nf][3];
                }
        }
        __syncthreads();
        const int r = tid>>1, c0 = (tid&1)*32;
        const int nbase = n0 + hf*64;
        if (OP == 0) {
            const int Lm1 = (1 << lsh) - 1;
            int m = m0 + r, bb = m >> lsh, tok = m & Lm1;
            int hh = nbase >> 6;
            size_t o = (((size_t)(bb*H_ + hh) << lsh) + tok) * 64 + c0;
            #pragma unroll
            for (int g8 = 0; g8 < 4; g8++) {
                float x[8];
                #pragma unroll
                for (int j = 0; j < 8; j++)
                    x[j] = alpha * (OS[r*68 + c0 + g8*8 + j]
                                    + __ldg(bias + nbase + c0 + g8*8 + j));
                *(uint4*)(Dh + o + g8*8) = pack8h(x);
            }
        } else {
            float* crow = C + (size_t)(m0+r)*N + nbase + c0;
            #pragma unroll
            for (int g4 = 0; g4 < 8; g4++) {
                float4 v;
                v.x = OS[r*68 + c0 + g4*4 + 0] + __ldg(bias + nbase + c0 + g4*4 + 0);
                v.y = OS[r*68 + c0 + g4*4 + 1] + __ldg(bias + nbase + c0 + g4*4 + 1);
                v.z = OS[r*68 + c0 + g4*4 + 2] + __ldg(bias + nbase + c0 + g4*4 + 2);
                v.w = OS[r*68 + c0 + g4*4 + 3] + __ldg(bias + nbase + c0 + g4*4 + 3);
                *(float4*)(crow + g4*4) = v;
            }
        }
    }
}

struct PIArgs {
    const float *bvq, *bvv, *bak, *bav;
    float alq;
};
__global__ void __launch_bounds__(256,2) proj_in_all(PIArgs p)
{
    const int sel = blockIdx.x >> 2;
    if (blockIdx.y < 128) {
        proj_body<0>(g_vh, sel ? g_wvv : g_wvq, sel ? p.bvv : p.bvq, 0,
                     sel ? g_vv : g_q,
                     VD_, 512, blockIdx.y*128, (blockIdx.x & 3)*128,
                     sel ? 1.0f : p.alq, 11);
    } else {
        proj_body<0>(g_ah, sel ? g_wav : g_wak, sel ? p.bav : p.bak, 0,
                     sel ? g_va : g_k,
                     AD_, 512, (blockIdx.y-128)*128, (blockIdx.x & 3)*128,
                     1.0f, 9);
    }
}

__global__ void __launch_bounds__(256,2) proj_out2(
    const float* b1, float* C1, const float* b2, float* C2)
{
    const bool r2 = blockIdx.y >= 128;
    if (r2 && blockIdx.x >= 2) return;
    proj_body<1>(r2 ? g_oa : g_ov, r2 ? g_woa : g_wov,
                 r2 ? b2 : b1, r2 ? C2 : C1, 0,
                 512, r2 ? 256 : 512,
                 (r2 ? blockIdx.y - 128 : blockIdx.y)*128, blockIdx.x*128,
                 1.0f, 0);
}

// ---------------------------------------------------------------------------
extern "C" void kernel_launch(void* const* d_in, const int* in_sizes, int n_in,
                              void* d_out, int out_size)
{
    const float* v    = (const float*)d_in[0];
    const float* a    = (const float*)d_in[1];
    const float* w_vq = (const float*)d_in[2];
    const float* b_vq = (const float*)d_in[3];
    const float* w_ak = (const float*)d_in[4];
    const float* b_ak = (const float*)d_in[5];
    const float* w_vv = (const float*)d_in[6];
    const float* b_vv = (const float*)d_in[7];
    const float* w_av = (const float*)d_in[8];
    const float* b_av = (const float*)d_in[9];
    const float* w_ov = (const float*)d_in[10];
    const float* b_ov = (const float*)d_in[11];
    const float* w_oa = (const float*)d_in[12];
    const float* b_oa = (const float*)d_in[13];
    float* out = (float*)d_out;

    __half *vh, *ah, *wvq, *wak, *wvv, *wav, *wov, *woa;
    cudaGetSymbolAddress((void**)&vh,  g_vh);  cudaGetSymbolAddress((void**)&ah,  g_ah);
    cudaGetSymbolAddress((void**)&wvq, g_wvq); cudaGetSymbolAddress((void**)&wak, g_wak);
    cudaGetSymbolAddress((void**)&wvv, g_wvv); cudaGetSymbolAddress((void**)&wav, g_wav);
    cudaGetSymbolAddress((void**)&wov, g_wov); cudaGetSymbolAddress((void**)&woa, g_woa);

    cudaFuncSetAttribute(proj_in_all, cudaFuncAttributeMaxDynamicSharedMemorySize, PJ_SZ);
    cudaFuncSetAttribute(proj_out2,   cudaFuncAttributeMaxDynamicSharedMemorySize, PJ_SZ);
    cudaFuncSetAttribute(scores_outa, cudaFuncAttributeMaxDynamicSharedMemorySize, SO_SZ);
    cudaFuncSetAttribute(gemm_outv,   cudaFuncAttributeMaxDynamicSharedMemorySize, FV_SZ);

    CvArgs ca;
    const float* srcs[8] = { v, a, w_vq, w_ak, w_vv, w_av, w_ov, w_oa };
    __half* dsts[8]      = { vh, ah, wvq, wak, wvv, wav, wov, woa };
    int nblk[8] = { B_*T_*VD_/2048, B_*S_*AD_/2048,
                    VD_*E_/2048, AD_*E_/2048, VD_*E_/2048, AD_*E_/2048,
                    E_*VD_/2048, E_*AD_/2048 };
    int acc0 = 0;
    for (int i = 0; i < 8; i++) { ca.s[i] = srcs[i]; ca.d[i] = dsts[i];
                                  ca.boff[i] = acc0; acc0 += nblk[i]; }
    ca.boff[8] = acc0;
    f2h_all<<<acc0, 256>>>(ca);

    PIArgs pa{ b_vq, b_vv, b_ak, b_av, 0.125f * 1.4426950408889634f };
    proj_in_all<<<dim3(8,160), 256, PJ_SZ>>>(pa);

    scores_outa<<<dim3(4, BH_), 256, SO_SZ>>>();
    gemm_outv  <<<dim3(T_/128, BH_), 256, FV_SZ>>>();

    proj_out2<<<dim3(4,160), 256, PJ_SZ>>>(b_ov, out,
                                           b_oa, out + (size_t)B_*T_*VD_);
}